// round 11
// baseline (speedup 1.0000x reference)
#include <cuda_runtime.h>
#include <cuda_bf16.h>
#include <cstdint>

#define B_    4
#define CIN   1536
#define HIDF  1536
#define OUTF  512
#define HH    64
#define NN    4096
#define MROWS (B_ * NN)      // 16384

// ---------------- GEMM tile config: CTA 128x128, warp 64x64, BK16 -----------
#define BMt 128
#define BNt 128
#define BKt 16
#define NKT (CIN / BKt)          // 96
#define ROWPITCH 48              // 32B data + 16B pad; 16-aligned; conflict-free
#define ARRB (128 * ROWPITCH)    // 6144 per operand array
#define STG_BYTES (4 * ARRB)     // 24576
#define NSTAGE 4
#define SMEM_GMM (NSTAGE * STG_BYTES)   // 98304 (x2 CTA = 196KB/SM)
#define EP_P 130                 // epilogue staging pitch (floats)

// ---------------- scratch ----------------------------------------------------
__device__ __nv_bfloat16 g_xth[(size_t)MROWS * CIN];
__device__ __nv_bfloat16 g_xtl[(size_t)MROWS * CIN];
__device__ __nv_bfloat16 g_Sh [(size_t)MROWS * CIN];
__device__ __nv_bfloat16 g_Sl [(size_t)MROWS * CIN];
__device__ float         g_H1 [(size_t)MROWS * HIDF];
__device__ __nv_bfloat16 g_Th [(size_t)MROWS * HIDF];
__device__ __nv_bfloat16 g_Tl [(size_t)MROWS * HIDF];
__device__ float         g_orT[(size_t)OUTF * MROWS];   // origin f-major [f][m]
__device__ __nv_bfloat16 g_W1h[(size_t)HIDF * CIN];
__device__ __nv_bfloat16 g_W1l[(size_t)HIDF * CIN];
__device__ __nv_bfloat16 g_W2h[(size_t)OUTF * CIN];
__device__ __nv_bfloat16 g_W2l[(size_t)OUTF * CIN];
__device__ __nv_bfloat16 g_Wlh[(size_t)OUTF * CIN];
__device__ __nv_bfloat16 g_Wll[(size_t)OUTF * CIN];

// ---------------- helpers ----------------------------------------------------
__device__ __forceinline__ uint32_t smem_u32(const void* p) {
    uint32_t a;
    asm("{ .reg .u64 t; cvta.to.shared.u64 t, %1; cvt.u32.u64 %0, t; }" : "=r"(a) : "l"(p));
    return a;
}
__device__ __forceinline__ void cp16(uint32_t dst, const void* src) {
    asm volatile("cp.async.cg.shared.global [%0], [%1], 16;" :: "r"(dst), "l"(src));
}
#define CP_COMMIT() asm volatile("cp.async.commit_group;" ::: "memory")

#define LDSM4(r0, r1, r2, r3, a)                                           \
    asm volatile("ldmatrix.sync.aligned.m8n8.x4.shared.b16 {%0,%1,%2,%3}, [%4];" \
                 : "=r"(r0), "=r"(r1), "=r"(r2), "=r"(r3) : "r"(a))

#define MMA(d, a, b0, b1)                                                  \
    asm volatile("mma.sync.aligned.m16n8k16.row.col.f32.bf16.bf16.f32 "    \
                 "{%0,%1,%2,%3},{%4,%5,%6,%7},{%8,%9},{%0,%1,%2,%3};"      \
                 : "+f"((d)[0]), "+f"((d)[1]), "+f"((d)[2]), "+f"((d)[3])  \
                 : "r"((a)[0]), "r"((a)[1]), "r"((a)[2]), "r"((a)[3]),     \
                   "r"(b0), "r"(b1))

__device__ __forceinline__ void split1(float v, __nv_bfloat16& h, __nv_bfloat16& l) {
    h = __float2bfloat16_rn(v);
    l = __float2bfloat16_rn(v - __bfloat162float(h));
}

// ---------------- transpose in: x [B,C,N] -> xth/xtl [B,N,C] ----------------
__global__ void k_tin(const float* __restrict__ x) {
    __shared__ float tile[32][33];
    int b = blockIdx.z, n0 = blockIdx.x << 5, c0 = blockIdx.y << 5;
    int tx = threadIdx.x, ty = threadIdx.y;
    const float* xb = x + (size_t)b * CIN * NN;
#pragma unroll
    for (int i = ty; i < 32; i += 8)
        tile[i][tx] = xb[(size_t)(c0 + i) * NN + (n0 + tx)];
    __syncthreads();
    size_t ob = (size_t)b * NN * CIN;
#pragma unroll
    for (int i = ty; i < 32; i += 8) {
        float v = tile[tx][i];
        size_t idx = ob + (size_t)(n0 + i) * CIN + (c0 + tx);
        __nv_bfloat16 h, l; split1(v, h, l);
        g_xth[idx] = h; g_xtl[idx] = l;
    }
}

// ---------------- weight prep: W [K,Nc] -> Wt hi/lo [Nc,K] ------------------
__global__ void k_wt(const float* __restrict__ W, __nv_bfloat16* __restrict__ oh,
                     __nv_bfloat16* __restrict__ ol, int Nc) {
    __shared__ float tile[32][33];
    int n0 = blockIdx.x << 5, k0 = blockIdx.y << 5;
    int tx = threadIdx.x, ty = threadIdx.y;
#pragma unroll
    for (int i = ty; i < 32; i += 8)
        tile[i][tx] = W[(size_t)(k0 + i) * Nc + (n0 + tx)];
    __syncthreads();
#pragma unroll
    for (int i = ty; i < 32; i += 8) {
        float v = tile[tx][i];
        size_t idx = (size_t)(n0 + i) * CIN + (k0 + tx);
        __nv_bfloat16 h, l; split1(v, h, l);
        oh[idx] = h; ol[idx] = l;
    }
}

// ---------------- 5-point GCN stencil -> bf16 hi/lo -------------------------
// IN=0: fp32 input (float4).  IN=1: bf16 hi/lo pair input.
__device__ __forceinline__ int degat(int r, int c) {
    return 1 + (r > 0) + (r < HH - 1) + (c > 0) + (c < HH - 1);
}

template <int IN>
__global__ void k_st(const float4* __restrict__ inf,
                     const __nv_bfloat16* __restrict__ inh,
                     const __nv_bfloat16* __restrict__ inl,
                     __nv_bfloat16* __restrict__ oh, __nv_bfloat16* __restrict__ ol) {
    const int C4 = CIN / 4;          // 384 (CIN == HIDF)
    int n = blockIdx.x, b = blockIdx.y, t = threadIdx.x;
    int r = n >> 6, c = n & 63;
    int dg = degat(r, c);
    size_t base = (size_t)b * NN * C4;

    float4 acc;
    {
        float4 v;
        if (IN == 0) v = inf[base + (size_t)n * C4 + t];
        else {
            uint2 hh = ((const uint2*)inh)[base + (size_t)n * C4 + t];
            uint2 ll = ((const uint2*)inl)[base + (size_t)n * C4 + t];
            __nv_bfloat162 h0 = *(__nv_bfloat162*)&hh.x, h1 = *(__nv_bfloat162*)&hh.y;
            __nv_bfloat162 l0 = *(__nv_bfloat162*)&ll.x, l1 = *(__nv_bfloat162*)&ll.y;
            float2 a0 = __bfloat1622float2(h0), a1 = __bfloat1622float2(h1);
            float2 c0 = __bfloat1622float2(l0), c1 = __bfloat1622float2(l1);
            v = make_float4(a0.x + c0.x, a0.y + c0.y, a1.x + c1.x, a1.y + c1.y);
        }
        float wc = 1.0f / (float)dg;
        acc = make_float4(v.x * wc, v.y * wc, v.z * wc, v.w * wc);
    }
#define NBR(nm, dr, dc)                                                    \
    {                                                                      \
        int dn = degat(r + (dr), c + (dc));                                \
        float w = rsqrtf((float)(dg * dn));                                \
        float4 u;                                                          \
        if (IN == 0) u = inf[base + (size_t)(nm) * C4 + t];                \
        else {                                                             \
            uint2 hh = ((const uint2*)inh)[base + (size_t)(nm) * C4 + t];  \
            uint2 ll = ((const uint2*)inl)[base + (size_t)(nm) * C4 + t];  \
            __nv_bfloat162 h0 = *(__nv_bfloat162*)&hh.x, h1 = *(__nv_bfloat162*)&hh.y; \
            __nv_bfloat162 l0 = *(__nv_bfloat162*)&ll.x, l1 = *(__nv_bfloat162*)&ll.y; \
            float2 a0 = __bfloat1622float2(h0), a1 = __bfloat1622float2(h1);           \
            float2 c0 = __bfloat1622float2(l0), c1 = __bfloat1622float2(l1);           \
            u = make_float4(a0.x + c0.x, a0.y + c0.y, a1.x + c1.x, a1.y + c1.y);       \
        }                                                                  \
        acc.x += u.x * w; acc.y += u.y * w;                                \
        acc.z += u.z * w; acc.w += u.w * w;                                \
    }
    if (r > 0)  NBR(n - 64, -1, 0);
    if (r < 63) NBR(n + 64, +1, 0);
    if (c > 0)  NBR(n - 1, 0, -1);
    if (c < 63) NBR(n + 1, 0, +1);
#undef NBR
    __nv_bfloat16 hx, lx, hy, ly, hz, lz, hw, lw;
    split1(acc.x, hx, lx); split1(acc.y, hy, ly);
    split1(acc.z, hz, lz); split1(acc.w, hw, lw);
    uint32_t h01 = ((uint32_t)__bfloat16_as_ushort(hy) << 16) | __bfloat16_as_ushort(hx);
    uint32_t h23 = ((uint32_t)__bfloat16_as_ushort(hw) << 16) | __bfloat16_as_ushort(hz);
    uint32_t l01 = ((uint32_t)__bfloat16_as_ushort(ly) << 16) | __bfloat16_as_ushort(lx);
    uint32_t l23 = ((uint32_t)__bfloat16_as_ushort(lw) << 16) | __bfloat16_as_ushort(lz);
    size_t idx = base + (size_t)n * C4 + t;
    ((uint2*)oh)[idx] = make_uint2(h01, h23);
    ((uint2*)ol)[idx] = make_uint2(l01, l23);
}

// ---------------- HMMA split-bf16 GEMM, 128 thr, 2 CTA/SM -------------------
// D[m,n] = sum_k A[m,k]*B[n,k] via AhBh + AlBh + AhBl, fp32 reg accum,
// smem-staged fully-coalesced epilogues:
// EPI 0: C[m][Nc] = relu(acc+bias[f]) + (auxh+auxl)[m][Nc]
// EPI 1: C[f][MROWS] = acc + bias[f]                      (f-major)
// EPI 2: out[(b*OUTF+f)*NN + n] = (acc+bias[f]) * auxf[f][MROWS]
template <int EPI>
__global__ __launch_bounds__(128, 2) void k_gmm(
    const __nv_bfloat16* __restrict__ Ah, const __nv_bfloat16* __restrict__ Al,
    const __nv_bfloat16* __restrict__ Bh, const __nv_bfloat16* __restrict__ Bl,
    const float* __restrict__ bias, const float* __restrict__ auxf,
    const __nv_bfloat16* __restrict__ auxh, const __nv_bfloat16* __restrict__ auxl,
    float* __restrict__ C, int Nc)
{
    extern __shared__ char smem[];
    uint32_t sb = smem_u32(smem);
    int tid = threadIdx.x, wid = tid >> 5, lane = tid & 31;
    int bm = blockIdx.y * BMt, bn = blockIdx.x * BNt;

    // ---- producer: 8 x 16B cp.async per thread per stage ----
    const __nv_bfloat16* psrc[8];
    uint32_t pdst[8];
#pragma unroll
    for (int j = 0; j < 8; j++) {
        int c   = tid + j * 128;      // 0..1023
        int row = c >> 1, half = c & 1;
        int arr = row >> 7, r = row & 127;
        const __nv_bfloat16* base =
            (arr == 0) ? Ah : (arr == 1) ? Al : (arr == 2) ? Bh : Bl;
        int r0 = (arr < 2) ? bm : bn;
        psrc[j] = base + (size_t)(r0 + r) * CIN + half * 8;
        pdst[j] = (uint32_t)(arr * ARRB + r * ROWPITCH + half * 16);   // 16-aligned
    }

#define ISSUE(stg, kt)                                                     \
    {                                                                      \
        uint32_t stb_ = sb + (stg) * STG_BYTES;                            \
        _Pragma("unroll")                                                  \
        for (int j = 0; j < 8; j++)                                        \
            cp16(stb_ + pdst[j], psrc[j] + (kt) * BKt);                    \
        CP_COMMIT();                                                       \
    }

    ISSUE(0, 0); ISSUE(1, 1); ISSUE(2, 2);

    // ---- consumer addressing: warp (wm, wn) owns 64x64 ----
    int wm = wid & 1, wn = wid >> 1;
    uint32_t a_base = (uint32_t)((wm * 64 + (lane & 15)) * ROWPITCH + ((lane >> 4) << 4));
    uint32_t b_base = (uint32_t)(2 * ARRB +
        (wn * 64 + ((lane & 7) | ((lane >> 4) << 3))) * ROWPITCH + (((lane >> 3) & 1) << 4));

    float acc[4][8][4];
#pragma unroll
    for (int mi = 0; mi < 4; mi++)
#pragma unroll
        for (int nt = 0; nt < 8; nt++)
#pragma unroll
            for (int q = 0; q < 4; q++) acc[mi][nt][q] = 0.f;

    int s_cur = 0, s_nxt = 3;
#pragma unroll 1
    for (int kt = 0; kt < NKT; kt++) {
        int rem = NKT - 1 - kt;
        if (rem >= 2)      asm volatile("cp.async.wait_group 2;" ::: "memory");
        else if (rem == 1) asm volatile("cp.async.wait_group 1;" ::: "memory");
        else               asm volatile("cp.async.wait_group 0;" ::: "memory");
        __syncthreads();
        if (kt + 3 < NKT) ISSUE(s_nxt, kt + 3);

        uint32_t st = sb + s_cur * STG_BYTES;
        uint32_t ah[4][4], al[4][4], bh[8][2], bl[8][2];
        uint32_t ak = st + a_base;
#pragma unroll
        for (int mi = 0; mi < 4; mi++) {
            LDSM4(ah[mi][0], ah[mi][1], ah[mi][2], ah[mi][3], ak + mi * (16 * ROWPITCH));
            LDSM4(al[mi][0], al[mi][1], al[mi][2], al[mi][3],
                  ak + ARRB + mi * (16 * ROWPITCH));
        }
        uint32_t bk = st + b_base;
#pragma unroll
        for (int j = 0; j < 4; j++) {
            uint32_t r0, r1, r2, r3;
            LDSM4(r0, r1, r2, r3, bk + j * (16 * ROWPITCH));
            bh[j * 2][0] = r0;     bh[j * 2][1] = r1;
            bh[j * 2 + 1][0] = r2; bh[j * 2 + 1][1] = r3;
            LDSM4(r0, r1, r2, r3, bk + ARRB + j * (16 * ROWPITCH));
            bl[j * 2][0] = r0;     bl[j * 2][1] = r1;
            bl[j * 2 + 1][0] = r2; bl[j * 2 + 1][1] = r3;
        }
#pragma unroll
        for (int mi = 0; mi < 4; mi++)
#pragma unroll
            for (int nt = 0; nt < 8; nt++)
                MMA(acc[mi][nt], ah[mi], bh[nt][0], bh[nt][1]);
#pragma unroll
        for (int mi = 0; mi < 4; mi++)
#pragma unroll
            for (int nt = 0; nt < 8; nt++)
                MMA(acc[mi][nt], al[mi], bh[nt][0], bh[nt][1]);
#pragma unroll
        for (int mi = 0; mi < 4; mi++)
#pragma unroll
            for (int nt = 0; nt < 8; nt++)
                MMA(acc[mi][nt], ah[mi], bl[nt][0], bl[nt][1]);

        s_cur = (s_cur == NSTAGE - 1) ? 0 : s_cur + 1;
        s_nxt = (s_nxt == NSTAGE - 1) ? 0 : s_nxt + 1;
    }

    // ---- staged epilogue ----
    __syncthreads();
    float* sep = (float*)smem;

    float bf[8][2];
#pragma unroll
    for (int nt = 0; nt < 8; nt++)
#pragma unroll
        for (int ql = 0; ql < 2; ql++)
            bf[nt][ql] = __ldg(&bias[bn + wn * 64 + nt * 8 + ((lane & 3) << 1) + ql]);

#pragma unroll
    for (int mi = 0; mi < 4; mi++)
#pragma unroll
        for (int nt = 0; nt < 8; nt++)
#pragma unroll
            for (int q = 0; q < 4; q++) {
                int m_l = wm * 64 + mi * 16 + (lane >> 2) + ((q >> 1) << 3);
                int f_l = wn * 64 + nt * 8 + ((lane & 3) << 1) + (q & 1);
                float v = acc[mi][nt][q] + bf[nt][q & 1];
                if (EPI == 0) sep[m_l * EP_P + f_l] = v;
                else          sep[f_l * EP_P + m_l] = v;
            }
    __syncthreads();

    if (EPI == 0) {
#pragma unroll 1
        for (int rr = 0; rr < 32; rr++) {
            int m = wid * 32 + rr;
#pragma unroll
            for (int fo = 0; fo < 128; fo += 32) {
                int f = fo + lane;
                float v = sep[m * EP_P + f];
                size_t gi = (size_t)(bm + m) * Nc + bn + f;
                v = fmaxf(v, 0.f) + __bfloat162float(auxh[gi]) + __bfloat162float(auxl[gi]);
                C[gi] = v;
            }
        }
    } else if (EPI == 1) {
#pragma unroll 1
        for (int rr = 0; rr < 32; rr++) {
            int f = wid * 32 + rr;
            size_t rowb = (size_t)(bn + f) * MROWS + bm;
#pragma unroll
            for (int mo = 0; mo < 128; mo += 32) {
                int m = mo + lane;
                C[rowb + m] = sep[f * EP_P + m];
            }
        }
    } else {
        int b0 = bm >> 12, nn0 = bm & (NN - 1);
#pragma unroll 1
        for (int rr = 0; rr < 32; rr++) {
            int f = wid * 32 + rr;
            int g = bn + f;
            size_t arow = (size_t)g * MROWS + bm;
            size_t orow = ((size_t)(b0 * OUTF + g)) * NN + nn0;
#pragma unroll
            for (int mo = 0; mo < 128; mo += 32) {
                int m = mo + lane;
                C[orow + m] = sep[f * EP_P + m] * auxf[arow + m];
            }
        }
    }
#undef ISSUE
}

// ---------------- launch -----------------------------------------------------
extern "C" void kernel_launch(void* const* d_in, const int* in_sizes, int n_in,
                              void* d_out, int out_size) {
    const float* x  = (const float*)d_in[0];
    const float* W1 = (const float*)d_in[1];
    const float* b1 = (const float*)d_in[2];
    const float* W2 = (const float*)d_in[3];
    const float* b2 = (const float*)d_in[4];
    const float* Wl = (const float*)d_in[5];
    const float* bl = (const float*)d_in[6];
    float* out = (float*)d_out;

    float *p_H1, *p_orT;
    __nv_bfloat16 *p_xth, *p_xtl, *p_Sh, *p_Sl, *p_Th, *p_Tl;
    __nv_bfloat16 *p_W1h, *p_W1l, *p_W2h, *p_W2l, *p_Wlh, *p_Wll;
    cudaGetSymbolAddress((void**)&p_xth, g_xth);
    cudaGetSymbolAddress((void**)&p_xtl, g_xtl);
    cudaGetSymbolAddress((void**)&p_Sh,  g_Sh);
    cudaGetSymbolAddress((void**)&p_Sl,  g_Sl);
    cudaGetSymbolAddress((void**)&p_H1,  g_H1);
    cudaGetSymbolAddress((void**)&p_Th,  g_Th);
    cudaGetSymbolAddress((void**)&p_Tl,  g_Tl);
    cudaGetSymbolAddress((void**)&p_orT, g_orT);
    cudaGetSymbolAddress((void**)&p_W1h, g_W1h);
    cudaGetSymbolAddress((void**)&p_W1l, g_W1l);
    cudaGetSymbolAddress((void**)&p_W2h, g_W2h);
    cudaGetSymbolAddress((void**)&p_W2l, g_W2l);
    cudaGetSymbolAddress((void**)&p_Wlh, g_Wlh);
    cudaGetSymbolAddress((void**)&p_Wll, g_Wll);

    cudaFuncSetAttribute(k_gmm<0>, cudaFuncAttributeMaxDynamicSharedMemorySize, SMEM_GMM);
    cudaFuncSetAttribute(k_gmm<1>, cudaFuncAttributeMaxDynamicSharedMemorySize, SMEM_GMM);
    cudaFuncSetAttribute(k_gmm<2>, cudaFuncAttributeMaxDynamicSharedMemorySize, SMEM_GMM);

    // input transpose + split (bf16 hi/lo only)
    k_tin<<<dim3(NN / 32, CIN / 32, B_), dim3(32, 8)>>>(x);
    // weight transposes + splits
    k_wt<<<dim3(HIDF / 32, CIN / 32), dim3(32, 8)>>>(W1, p_W1h, p_W1l, HIDF);
    k_wt<<<dim3(OUTF / 32, CIN / 32), dim3(32, 8)>>>(W2, p_W2h, p_W2l, OUTF);
    k_wt<<<dim3(OUTF / 32, CIN / 32), dim3(32, 8)>>>(Wl, p_Wlh, p_Wll, OUTF);
    // S = stencil(xh + xl)
    k_st<1><<<dim3(NN, B_), CIN / 4>>>(nullptr, p_xth, p_xtl, p_Sh, p_Sl);
    // H1 = relu(S@W1 + b1) + (xh+xl)
    k_gmm<0><<<dim3(HIDF / BNt, MROWS / BMt), 128, SMEM_GMM>>>(
        p_Sh, p_Sl, p_W1h, p_W1l, b1, nullptr, p_xth, p_xtl, p_H1, HIDF);
    // T = stencil(H1)
    k_st<0><<<dim3(NN, B_), HIDF / 4>>>((const float4*)p_H1, nullptr, nullptr, p_Th, p_Tl);
    // origin^T[f][m] = (xt@Wl + bl)^T
    k_gmm<1><<<dim3(OUTF / BNt, MROWS / BMt), 128, SMEM_GMM>>>(
        p_xth, p_xtl, p_Wlh, p_Wll, bl, nullptr, nullptr, nullptr, p_orT, OUTF);
    // out = (T@W2 + b2) * origin, coalesced NCHW writes
    k_gmm<2><<<dim3(OUTF / BNt, MROWS / BMt), 128, SMEM_GMM>>>(
        p_Th, p_Tl, p_W2h, p_W2l, b2, p_orT, nullptr, nullptr, out, OUTF);
}

// round 12
// speedup vs baseline: 1.0834x; 1.0834x over previous
#include <cuda_runtime.h>
#include <cuda_bf16.h>
#include <cstdint>

#define B_    4
#define CIN   1536
#define HIDF  1536
#define OUTF  512
#define HH    64
#define NN    4096
#define MROWS (B_ * NN)      // 16384

// ---------------- GEMM tile config (R7 mainloop, proven) --------------------
#define BMt 128
#define BNt 256
#define BKt 32
#define NKT (CIN / BKt)          // 48
#define ROWPITCH 80              // 64B data + 16B pad
#define OFF_AH 0
#define OFF_AL (128 * ROWPITCH)              // 10240
#define OFF_BH (2 * 128 * ROWPITCH)          // 20480
#define OFF_BL (OFF_BH + 256 * ROWPITCH)     // 40960
#define STG_BYTES (OFF_BL + 256 * ROWPITCH)  // 61440
#define NSTAGE 3
#define SMEM_GMM (NSTAGE * STG_BYTES)        // 184320

// ---------------- scratch ----------------------------------------------------
__device__ __nv_bfloat16 g_xth[(size_t)MROWS * CIN];
__device__ __nv_bfloat16 g_xtl[(size_t)MROWS * CIN];
__device__ __nv_bfloat16 g_Sh [(size_t)MROWS * CIN];
__device__ __nv_bfloat16 g_Sl [(size_t)MROWS * CIN];
__device__ float         g_H1 [(size_t)MROWS * HIDF];
__device__ __nv_bfloat16 g_Th [(size_t)MROWS * HIDF];
__device__ __nv_bfloat16 g_Tl [(size_t)MROWS * HIDF];
__device__ float         g_orT[(size_t)OUTF * MROWS];   // origin f-major [f][m]
__device__ __nv_bfloat16 g_W1h[(size_t)HIDF * CIN];
__device__ __nv_bfloat16 g_W1l[(size_t)HIDF * CIN];
__device__ __nv_bfloat16 g_W2h[(size_t)OUTF * CIN];
__device__ __nv_bfloat16 g_W2l[(size_t)OUTF * CIN];
__device__ __nv_bfloat16 g_Wlh[(size_t)OUTF * CIN];
__device__ __nv_bfloat16 g_Wll[(size_t)OUTF * CIN];

// ---------------- helpers ----------------------------------------------------
__device__ __forceinline__ uint32_t smem_u32(const void* p) {
    uint32_t a;
    asm("{ .reg .u64 t; cvta.to.shared.u64 t, %1; cvt.u32.u64 %0, t; }" : "=r"(a) : "l"(p));
    return a;
}
__device__ __forceinline__ void cp16(uint32_t dst, const void* src) {
    asm volatile("cp.async.cg.shared.global [%0], [%1], 16;" :: "r"(dst), "l"(src));
}
#define CP_COMMIT() asm volatile("cp.async.commit_group;" ::: "memory")
#define CP_WAIT1()  asm volatile("cp.async.wait_group 1;" ::: "memory")
#define CP_WAIT0()  asm volatile("cp.async.wait_group 0;" ::: "memory")

#define LDSM4(r0, r1, r2, r3, a)                                           \
    asm volatile("ldmatrix.sync.aligned.m8n8.x4.shared.b16 {%0,%1,%2,%3}, [%4];" \
                 : "=r"(r0), "=r"(r1), "=r"(r2), "=r"(r3) : "r"(a))

#define MMA(d, a, b0, b1)                                                  \
    asm volatile("mma.sync.aligned.m16n8k16.row.col.f32.bf16.bf16.f32 "    \
                 "{%0,%1,%2,%3},{%4,%5,%6,%7},{%8,%9},{%0,%1,%2,%3};"      \
                 : "+f"((d)[0]), "+f"((d)[1]), "+f"((d)[2]), "+f"((d)[3])  \
                 : "r"((a)[0]), "r"((a)[1]), "r"((a)[2]), "r"((a)[3]),     \
                   "r"(b0), "r"(b1))

__device__ __forceinline__ void split1(float v, __nv_bfloat16& h, __nv_bfloat16& l) {
    h = __float2bfloat16_rn(v);
    l = __float2bfloat16_rn(v - __bfloat162float(h));
}

// ---------------- transpose in: x [B,C,N] -> xth/xtl [B,N,C] ----------------
__global__ void k_tin(const float* __restrict__ x) {
    __shared__ float tile[32][33];
    int b = blockIdx.z, n0 = blockIdx.x << 5, c0 = blockIdx.y << 5;
    int tx = threadIdx.x, ty = threadIdx.y;
    const float* xb = x + (size_t)b * CIN * NN;
#pragma unroll
    for (int i = ty; i < 32; i += 8)
        tile[i][tx] = xb[(size_t)(c0 + i) * NN + (n0 + tx)];
    __syncthreads();
    size_t ob = (size_t)b * NN * CIN;
#pragma unroll
    for (int i = ty; i < 32; i += 8) {
        float v = tile[tx][i];
        size_t idx = ob + (size_t)(n0 + i) * CIN + (c0 + tx);
        __nv_bfloat16 h, l; split1(v, h, l);
        g_xth[idx] = h; g_xtl[idx] = l;
    }
}

// ---------------- weight prep: W [K,Nc] -> Wt hi/lo [Nc,K] ------------------
__global__ void k_wt(const float* __restrict__ W, __nv_bfloat16* __restrict__ oh,
                     __nv_bfloat16* __restrict__ ol, int Nc) {
    __shared__ float tile[32][33];
    int n0 = blockIdx.x << 5, k0 = blockIdx.y << 5;
    int tx = threadIdx.x, ty = threadIdx.y;
#pragma unroll
    for (int i = ty; i < 32; i += 8)
        tile[i][tx] = W[(size_t)(k0 + i) * Nc + (n0 + tx)];
    __syncthreads();
#pragma unroll
    for (int i = ty; i < 32; i += 8) {
        float v = tile[tx][i];
        size_t idx = (size_t)(n0 + i) * CIN + (k0 + tx);
        __nv_bfloat16 h, l; split1(v, h, l);
        oh[idx] = h; ol[idx] = l;
    }
}

// ---------------- 5-point GCN stencil -> bf16 hi/lo -------------------------
// IN=0: fp32 input (float4).  IN=1: bf16 hi/lo pair input.
__device__ __forceinline__ int degat(int r, int c) {
    return 1 + (r > 0) + (r < HH - 1) + (c > 0) + (c < HH - 1);
}

template <int IN>
__global__ void k_st(const float4* __restrict__ inf,
                     const __nv_bfloat16* __restrict__ inh,
                     const __nv_bfloat16* __restrict__ inl,
                     __nv_bfloat16* __restrict__ oh, __nv_bfloat16* __restrict__ ol) {
    const int C4 = CIN / 4;          // 384 (CIN == HIDF)
    int n = blockIdx.x, b = blockIdx.y, t = threadIdx.x;
    int r = n >> 6, c = n & 63;
    int dg = degat(r, c);
    size_t base = (size_t)b * NN * C4;

    float4 acc;
    {
        float4 v;
        if (IN == 0) v = inf[base + (size_t)n * C4 + t];
        else {
            uint2 hh = ((const uint2*)inh)[base + (size_t)n * C4 + t];
            uint2 ll = ((const uint2*)inl)[base + (size_t)n * C4 + t];
            __nv_bfloat162 h0 = *(__nv_bfloat162*)&hh.x, h1 = *(__nv_bfloat162*)&hh.y;
            __nv_bfloat162 l0 = *(__nv_bfloat162*)&ll.x, l1 = *(__nv_bfloat162*)&ll.y;
            float2 a0 = __bfloat1622float2(h0), a1 = __bfloat1622float2(h1);
            float2 c0 = __bfloat1622float2(l0), c1 = __bfloat1622float2(l1);
            v = make_float4(a0.x + c0.x, a0.y + c0.y, a1.x + c1.x, a1.y + c1.y);
        }
        float wc = 1.0f / (float)dg;
        acc = make_float4(v.x * wc, v.y * wc, v.z * wc, v.w * wc);
    }
#define NBR(nm, dr, dc)                                                    \
    {                                                                      \
        int dn = degat(r + (dr), c + (dc));                                \
        float w = rsqrtf((float)(dg * dn));                                \
        float4 u;                                                          \
        if (IN == 0) u = inf[base + (size_t)(nm) * C4 + t];                \
        else {                                                             \
            uint2 hh = ((const uint2*)inh)[base + (size_t)(nm) * C4 + t];  \
            uint2 ll = ((const uint2*)inl)[base + (size_t)(nm) * C4 + t];  \
            __nv_bfloat162 h0 = *(__nv_bfloat162*)&hh.x, h1 = *(__nv_bfloat162*)&hh.y; \
            __nv_bfloat162 l0 = *(__nv_bfloat162*)&ll.x, l1 = *(__nv_bfloat162*)&ll.y; \
            float2 a0 = __bfloat1622float2(h0), a1 = __bfloat1622float2(h1);           \
            float2 c0 = __bfloat1622float2(l0), c1 = __bfloat1622float2(l1);           \
            u = make_float4(a0.x + c0.x, a0.y + c0.y, a1.x + c1.x, a1.y + c1.y);       \
        }                                                                  \
        acc.x += u.x * w; acc.y += u.y * w;                                \
        acc.z += u.z * w; acc.w += u.w * w;                                \
    }
    if (r > 0)  NBR(n - 64, -1, 0);
    if (r < 63) NBR(n + 64, +1, 0);
    if (c > 0)  NBR(n - 1, 0, -1);
    if (c < 63) NBR(n + 1, 0, +1);
#undef NBR
    __nv_bfloat16 hx, lx, hy, ly, hz, lz, hw, lw;
    split1(acc.x, hx, lx); split1(acc.y, hy, ly);
    split1(acc.z, hz, lz); split1(acc.w, hw, lw);
    uint32_t h01 = ((uint32_t)__bfloat16_as_ushort(hy) << 16) | __bfloat16_as_ushort(hx);
    uint32_t h23 = ((uint32_t)__bfloat16_as_ushort(hw) << 16) | __bfloat16_as_ushort(hz);
    uint32_t l01 = ((uint32_t)__bfloat16_as_ushort(ly) << 16) | __bfloat16_as_ushort(lx);
    uint32_t l23 = ((uint32_t)__bfloat16_as_ushort(lw) << 16) | __bfloat16_as_ushort(lz);
    size_t idx = base + (size_t)n * C4 + t;
    ((uint2*)oh)[idx] = make_uint2(h01, h23);
    ((uint2*)ol)[idx] = make_uint2(l01, l23);
}

// ---------------- HMMA split-bf16 GEMM, CTA 128x256, warp 64x64 -------------
// R7 mainloop (proven), staged coalesced epilogues:
// EPI 0: C[m][Nc]   = relu(acc+bias[f]) + (auxh+auxl)[m][Nc]
// EPI 1: C[f][MROWS]= acc + bias[f]                     (f-major)
// EPI 2: out[(b*OUTF+f)*NN + n] = (acc+bias[f]) * auxf[f][MROWS]
template <int EPI>
__global__ __launch_bounds__(256, 1) void k_gmm(
    const __nv_bfloat16* __restrict__ Ah, const __nv_bfloat16* __restrict__ Al,
    const __nv_bfloat16* __restrict__ Bh, const __nv_bfloat16* __restrict__ Bl,
    const float* __restrict__ bias, const float* __restrict__ auxf,
    const __nv_bfloat16* __restrict__ auxh, const __nv_bfloat16* __restrict__ auxl,
    float* __restrict__ C, int Nc)
{
    extern __shared__ char smem[];
    uint32_t sb = smem_u32(smem);
    int tid = threadIdx.x, wid = tid >> 5, lane = tid & 31;
    int bm = blockIdx.y * BMt, bn = blockIdx.x * BNt;

    // ---- producer addressing: 12 x 16B cp.async per thread per stage ----
    const __nv_bfloat16* psrc[12];
    uint32_t pdst[12];
#pragma unroll
    for (int j = 0; j < 12; j++) {
        int c = tid + j * 256;           // 0..3071
        const __nv_bfloat16* base;
        int row, r0;
        uint32_t off;
        if (c < 512)       { base = Ah; row = c >> 2;          r0 = bm; off = OFF_AH; }
        else if (c < 1024) { base = Al; row = (c - 512) >> 2;  r0 = bm; off = OFF_AL; }
        else if (c < 2048) { base = Bh; row = (c - 1024) >> 2; r0 = bn; off = OFF_BH; }
        else               { base = Bl; row = (c - 2048) >> 2; r0 = bn; off = OFF_BL; }
        int sl = c & 3;
        psrc[j] = base + (size_t)(r0 + row) * CIN + sl * 8;
        pdst[j] = off + (uint32_t)(row * ROWPITCH + sl * 16);
    }

#define ISSUE(stg, kt)                                                     \
    {                                                                      \
        uint32_t stb_ = sb + (stg) * STG_BYTES;                            \
        _Pragma("unroll")                                                  \
        for (int j = 0; j < 12; j++)                                       \
            cp16(stb_ + pdst[j], psrc[j] + (kt) * BKt);                    \
        CP_COMMIT();                                                       \
    }

    ISSUE(0, 0);
    ISSUE(1, 1);

    // ---- consumer addressing: warp (wm, wn) owns 64x64 ----
    int wm = wid & 1, wn = wid >> 1;
    uint32_t a_base = (uint32_t)((wm * 64 + (lane & 15)) * ROWPITCH + ((lane >> 4) << 4));
    uint32_t b_base = (uint32_t)(OFF_BH +
        (wn * 64 + ((lane & 7) | ((lane >> 4) << 3))) * ROWPITCH + (((lane >> 3) & 1) << 4));

    float acc[4][8][4];
#pragma unroll
    for (int mi = 0; mi < 4; mi++)
#pragma unroll
        for (int nt = 0; nt < 8; nt++)
#pragma unroll
            for (int q = 0; q < 4; q++) acc[mi][nt][q] = 0.f;

    for (int kt = 0; kt < NKT; kt++) {
        if (kt + 1 < NKT) CP_WAIT1(); else CP_WAIT0();
        __syncthreads();
        if (kt + 2 < NKT) ISSUE((kt + 2) % NSTAGE, kt + 2);

        uint32_t st = sb + (kt % NSTAGE) * STG_BYTES;
#pragma unroll
        for (int ks = 0; ks < 2; ks++) {
            uint32_t ah[4][4], al[4][4], bh[8][2];
            uint32_t ak = st + a_base + ks * 32;
#pragma unroll
            for (int mi = 0; mi < 4; mi++) {
                LDSM4(ah[mi][0], ah[mi][1], ah[mi][2], ah[mi][3], ak + mi * (16 * ROWPITCH));
                LDSM4(al[mi][0], al[mi][1], al[mi][2], al[mi][3],
                      ak + (OFF_AL - OFF_AH) + mi * (16 * ROWPITCH));
            }
            uint32_t bk = st + b_base + ks * 32;
#pragma unroll
            for (int j = 0; j < 4; j++) {
                uint32_t r0, r1, r2, r3;
                LDSM4(r0, r1, r2, r3, bk + j * (16 * ROWPITCH));
                bh[j * 2][0] = r0;     bh[j * 2][1] = r1;
                bh[j * 2 + 1][0] = r2; bh[j * 2 + 1][1] = r3;
            }
#pragma unroll
            for (int mi = 0; mi < 4; mi++)
#pragma unroll
                for (int nt = 0; nt < 8; nt++)
                    MMA(acc[mi][nt], ah[mi], bh[nt][0], bh[nt][1]);
#pragma unroll
            for (int mi = 0; mi < 4; mi++)
#pragma unroll
                for (int nt = 0; nt < 8; nt++)
                    MMA(acc[mi][nt], al[mi], bh[nt][0], bh[nt][1]);
            uint32_t bl[8][2];
#pragma unroll
            for (int j = 0; j < 4; j++) {
                uint32_t r0, r1, r2, r3;
                LDSM4(r0, r1, r2, r3, bk + (OFF_BL - OFF_BH) + j * (16 * ROWPITCH));
                bl[j * 2][0] = r0;     bl[j * 2][1] = r1;
                bl[j * 2 + 1][0] = r2; bl[j * 2 + 1][1] = r3;
            }
#pragma unroll
            for (int mi = 0; mi < 4; mi++)
#pragma unroll
                for (int nt = 0; nt < 8; nt++)
                    MMA(acc[mi][nt], ah[mi], bl[nt][0], bl[nt][1]);
        }
    }

    // ---- staged coalesced epilogue ----
    __syncthreads();
    float* sep = (float*)smem;
    const int EPP = (EPI == 0) ? (BNt + 2) : 130;   // m-major 128x258 / f-major 256x130

    float bf[8][2];
#pragma unroll
    for (int nt = 0; nt < 8; nt++)
#pragma unroll
        for (int ql = 0; ql < 2; ql++)
            bf[nt][ql] = __ldg(&bias[bn + wn * 64 + nt * 8 + ((lane & 3) << 1) + ql]);

#pragma unroll
    for (int mi = 0; mi < 4; mi++)
#pragma unroll
        for (int nt = 0; nt < 8; nt++)
#pragma unroll
            for (int q = 0; q < 4; q++) {
                int m_l = wm * 64 + mi * 16 + (lane >> 2) + ((q >> 1) << 3);
                int f_l = wn * 64 + nt * 8 + ((lane & 3) << 1) + (q & 1);
                float v = acc[mi][nt][q] + bf[nt][q & 1];
                if (EPI == 0) sep[m_l * EPP + f_l] = v;
                else          sep[f_l * EPP + m_l] = v;
            }
    __syncthreads();

    if (EPI == 0) {
        // rows: 8 warps x 16 rows; cols: 256 by 32 lanes
#pragma unroll 1
        for (int rr = 0; rr < 16; rr++) {
            int m = wid * 16 + rr;
#pragma unroll
            for (int fo = 0; fo < BNt; fo += 32) {
                int f = fo + lane;
                float v = sep[m * EPP + f];
                size_t gi = (size_t)(bm + m) * Nc + bn + f;
                v = fmaxf(v, 0.f) + __bfloat162float(auxh[gi]) + __bfloat162float(auxl[gi]);
                C[gi] = v;
            }
        }
    } else if (EPI == 1) {
        // f rows: 8 warps x 32 f; m: 128 by 32 lanes
#pragma unroll 1
        for (int rr = 0; rr < 32; rr++) {
            int f = wid * 32 + rr;
            size_t rowb = (size_t)(bn + f) * MROWS + bm;
#pragma unroll
            for (int mo = 0; mo < 128; mo += 32) {
                int m = mo + lane;
                C[rowb + m] = sep[f * EPP + m];
            }
        }
    } else {
        int b0 = bm >> 12, nn0 = bm & (NN - 1);
#pragma unroll 1
        for (int rr = 0; rr < 32; rr++) {
            int f = wid * 32 + rr;
            int g = bn + f;
            size_t arow = (size_t)g * MROWS + bm;
            size_t orow = ((size_t)(b0 * OUTF + g)) * NN + nn0;
#pragma unroll
            for (int mo = 0; mo < 128; mo += 32) {
                int m = mo + lane;
                C[orow + m] = sep[f * EPP + m] * auxf[arow + m];
            }
        }
    }
#undef ISSUE
}

// ---------------- launch -----------------------------------------------------
extern "C" void kernel_launch(void* const* d_in, const int* in_sizes, int n_in,
                              void* d_out, int out_size) {
    const float* x  = (const float*)d_in[0];
    const float* W1 = (const float*)d_in[1];
    const float* b1 = (const float*)d_in[2];
    const float* W2 = (const float*)d_in[3];
    const float* b2 = (const float*)d_in[4];
    const float* Wl = (const float*)d_in[5];
    const float* bl = (const float*)d_in[6];
    float* out = (float*)d_out;

    float *p_H1, *p_orT;
    __nv_bfloat16 *p_xth, *p_xtl, *p_Sh, *p_Sl, *p_Th, *p_Tl;
    __nv_bfloat16 *p_W1h, *p_W1l, *p_W2h, *p_W2l, *p_Wlh, *p_Wll;
    cudaGetSymbolAddress((void**)&p_xth, g_xth);
    cudaGetSymbolAddress((void**)&p_xtl, g_xtl);
    cudaGetSymbolAddress((void**)&p_Sh,  g_Sh);
    cudaGetSymbolAddress((void**)&p_Sl,  g_Sl);
    cudaGetSymbolAddress((void**)&p_H1,  g_H1);
    cudaGetSymbolAddress((void**)&p_Th,  g_Th);
    cudaGetSymbolAddress((void**)&p_Tl,  g_Tl);
    cudaGetSymbolAddress((void**)&p_orT, g_orT);
    cudaGetSymbolAddress((void**)&p_W1h, g_W1h);
    cudaGetSymbolAddress((void**)&p_W1l, g_W1l);
    cudaGetSymbolAddress((void**)&p_W2h, g_W2h);
    cudaGetSymbolAddress((void**)&p_W2l, g_W2l);
    cudaGetSymbolAddress((void**)&p_Wlh, g_Wlh);
    cudaGetSymbolAddress((void**)&p_Wll, g_Wll);

    cudaFuncSetAttribute(k_gmm<0>, cudaFuncAttributeMaxDynamicSharedMemorySize, SMEM_GMM);
    cudaFuncSetAttribute(k_gmm<1>, cudaFuncAttributeMaxDynamicSharedMemorySize, SMEM_GMM);
    cudaFuncSetAttribute(k_gmm<2>, cudaFuncAttributeMaxDynamicSharedMemorySize, SMEM_GMM);

    // input transpose + split (bf16 hi/lo only)
    k_tin<<<dim3(NN / 32, CIN / 32, B_), dim3(32, 8)>>>(x);
    // weight transposes + splits
    k_wt<<<dim3(HIDF / 32, CIN / 32), dim3(32, 8)>>>(W1, p_W1h, p_W1l, HIDF);
    k_wt<<<dim3(OUTF / 32, CIN / 32), dim3(32, 8)>>>(W2, p_W2h, p_W2l, OUTF);
    k_wt<<<dim3(OUTF / 32, CIN / 32), dim3(32, 8)>>>(Wl, p_Wlh, p_Wll, OUTF);
    // S = stencil(xh + xl)
    k_st<1><<<dim3(NN, B_), CIN / 4>>>(nullptr, p_xth, p_xtl, p_Sh, p_Sl);
    // H1 = relu(S@W1 + b1) + (xh+xl)
    k_gmm<0><<<dim3(HIDF / BNt, MROWS / BMt), 256, SMEM_GMM>>>(
        p_Sh, p_Sl, p_W1h, p_W1l, b1, nullptr, p_xth, p_xtl, p_H1, HIDF);
    // T = stencil(H1)
    k_st<0><<<dim3(NN, B_), HIDF / 4>>>((const float4*)p_H1, nullptr, nullptr, p_Th, p_Tl);
    // origin^T[f][m] = (xt@Wl + bl)^T
    k_gmm<1><<<dim3(OUTF / BNt, MROWS / BMt), 256, SMEM_GMM>>>(
        p_xth, p_xtl, p_Wlh, p_Wll, bl, nullptr, nullptr, nullptr, p_orT, OUTF);
    // out = (T@W2 + b2) * origin, coalesced NCHW writes
    k_gmm<2><<<dim3(OUTF / BNt, MROWS / BMt), 256, SMEM_GMM>>>(
        p_Th, p_Tl, p_W2h, p_W2l, b2, p_orT, nullptr, nullptr, out, OUTF);
}

// round 15
// speedup vs baseline: 1.2108x; 1.1175x over previous
#include <cuda_runtime.h>
#include <cuda_bf16.h>
#include <cstdint>

#define B_    4
#define CIN   1536
#define HIDF  1536
#define OUTF  512
#define HH    64
#define NN    4096
#define MROWS (B_ * NN)      // 16384

// ---------------- GEMM tile config (R7 mainloop, proven) --------------------
#define BMt 128
#define BNt 256
#define BKt 32
#define NKT (CIN / BKt)          // 48
#define ROWPITCH 80              // 64B data + 16B pad
#define OFF_AH 0
#define OFF_AL (128 * ROWPITCH)              // 10240
#define OFF_BH (2 * 128 * ROWPITCH)          // 20480
#define OFF_BL (OFF_BH + 256 * ROWPITCH)     // 40960
#define STG_BYTES (OFF_BL + 256 * ROWPITCH)  // 61440
#define NSTAGE 3
#define SMEM_GMM (NSTAGE * STG_BYTES)        // 184320
#define NB1 (HIDF / BNt)         // 6 role-0 column tiles in merged kernel

// ---------------- scratch ----------------------------------------------------
__device__ float         g_xt [(size_t)MROWS * CIN];
__device__ __nv_bfloat16 g_xth[(size_t)MROWS * CIN];
__device__ __nv_bfloat16 g_xtl[(size_t)MROWS * CIN];
__device__ __nv_bfloat16 g_Sh [(size_t)MROWS * CIN];
__device__ __nv_bfloat16 g_Sl [(size_t)MROWS * CIN];
__device__ float         g_H1 [(size_t)MROWS * HIDF];
__device__ __nv_bfloat16 g_Th [(size_t)MROWS * HIDF];
__device__ __nv_bfloat16 g_Tl [(size_t)MROWS * HIDF];
__device__ float         g_orT[(size_t)OUTF * MROWS];   // origin f-major [f][m]
__device__ __nv_bfloat16 g_W1h[(size_t)HIDF * CIN];
__device__ __nv_bfloat16 g_W1l[(size_t)HIDF * CIN];
__device__ __nv_bfloat16 g_W2h[(size_t)OUTF * CIN];
__device__ __nv_bfloat16 g_W2l[(size_t)OUTF * CIN];
__device__ __nv_bfloat16 g_Wlh[(size_t)OUTF * CIN];
__device__ __nv_bfloat16 g_Wll[(size_t)OUTF * CIN];

// ---------------- helpers ----------------------------------------------------
__device__ __forceinline__ uint32_t smem_u32(const void* p) {
    uint32_t a;
    asm("{ .reg .u64 t; cvta.to.shared.u64 t, %1; cvt.u32.u64 %0, t; }" : "=r"(a) : "l"(p));
    return a;
}
__device__ __forceinline__ void cp16(uint32_t dst, const void* src) {
    asm volatile("cp.async.cg.shared.global [%0], [%1], 16;" :: "r"(dst), "l"(src));
}
#define CP_COMMIT() asm volatile("cp.async.commit_group;" ::: "memory")
#define CP_WAIT1()  asm volatile("cp.async.wait_group 1;" ::: "memory")
#define CP_WAIT0()  asm volatile("cp.async.wait_group 0;" ::: "memory")

#define LDSM4(r0, r1, r2, r3, a)                                           \
    asm volatile("ldmatrix.sync.aligned.m8n8.x4.shared.b16 {%0,%1,%2,%3}, [%4];" \
                 : "=r"(r0), "=r"(r1), "=r"(r2), "=r"(r3) : "r"(a))

#define MMA(d, a, b0, b1)                                                  \
    asm volatile("mma.sync.aligned.m16n8k16.row.col.f32.bf16.bf16.f32 "    \
                 "{%0,%1,%2,%3},{%4,%5,%6,%7},{%8,%9},{%0,%1,%2,%3};"      \
                 : "+f"((d)[0]), "+f"((d)[1]), "+f"((d)[2]), "+f"((d)[3])  \
                 : "r"((a)[0]), "r"((a)[1]), "r"((a)[2]), "r"((a)[3]),     \
                   "r"(b0), "r"(b1))

__device__ __forceinline__ void split1(float v, __nv_bfloat16& h, __nv_bfloat16& l) {
    h = __float2bfloat16_rn(v);
    l = __float2bfloat16_rn(v - __bfloat162float(h));
}

// ---------------- transpose in: x [B,C,N] -> xt fp32 + hi/lo ----------------
__global__ void k_tin(const float* __restrict__ x) {
    __shared__ float tile[32][33];
    int b = blockIdx.z, n0 = blockIdx.x << 5, c0 = blockIdx.y << 5;
    int tx = threadIdx.x, ty = threadIdx.y;
    const float* xb = x + (size_t)b * CIN * NN;
#pragma unroll
    for (int i = ty; i < 32; i += 8)
        tile[i][tx] = xb[(size_t)(c0 + i) * NN + (n0 + tx)];
    __syncthreads();
    size_t ob = (size_t)b * NN * CIN;
#pragma unroll
    for (int i = ty; i < 32; i += 8) {
        float v = tile[tx][i];
        size_t idx = ob + (size_t)(n0 + i) * CIN + (c0 + tx);
        g_xt[idx] = v;
        __nv_bfloat16 h, l; split1(v, h, l);
        g_xth[idx] = h; g_xtl[idx] = l;
    }
}

// ---------------- weight prep: W [K,Nc] -> Wt hi/lo [Nc,K] ------------------
__global__ void k_wt(const float* __restrict__ W, __nv_bfloat16* __restrict__ oh,
                     __nv_bfloat16* __restrict__ ol, int Nc) {
    __shared__ float tile[32][33];
    int n0 = blockIdx.x << 5, k0 = blockIdx.y << 5;
    int tx = threadIdx.x, ty = threadIdx.y;
#pragma unroll
    for (int i = ty; i < 32; i += 8)
        tile[i][tx] = W[(size_t)(k0 + i) * Nc + (n0 + tx)];
    __syncthreads();
#pragma unroll
    for (int i = ty; i < 32; i += 8) {
        float v = tile[tx][i];
        size_t idx = (size_t)(n0 + i) * CIN + (k0 + tx);
        __nv_bfloat16 h, l; split1(v, h, l);
        oh[idx] = h; ol[idx] = l;
    }
}

// ---------------- 5-point GCN stencil (fp32 in) -> bf16 hi/lo ---------------
__device__ __forceinline__ int degat(int r, int c) {
    return 1 + (r > 0) + (r < HH - 1) + (c > 0) + (c < HH - 1);
}

__global__ void k_st(const float4* __restrict__ in,
                     __nv_bfloat16* __restrict__ oh, __nv_bfloat16* __restrict__ ol) {
    const int C4 = CIN / 4;
    int n = blockIdx.x, b = blockIdx.y, t = threadIdx.x;
    int r = n >> 6, c = n & 63;
    int dg = degat(r, c);
    size_t base = (size_t)b * NN * C4;
    const float4* pin = in + base;

    float4 v = pin[(size_t)n * C4 + t];
    float wc = 1.0f / (float)dg;
    float4 acc = make_float4(v.x * wc, v.y * wc, v.z * wc, v.w * wc);
#define NBR(nm, dr, dc)                                      \
    {                                                        \
        int dn = degat(r + (dr), c + (dc));                  \
        float w = rsqrtf((float)(dg * dn));                  \
        float4 u = pin[(size_t)(nm) * C4 + t];               \
        acc.x += u.x * w; acc.y += u.y * w;                  \
        acc.z += u.z * w; acc.w += u.w * w;                  \
    }
    if (r > 0)  NBR(n - 64, -1, 0);
    if (r < 63) NBR(n + 64, +1, 0);
    if (c > 0)  NBR(n - 1, 0, -1);
    if (c < 63) NBR(n + 1, 0, +1);
#undef NBR
    __nv_bfloat16 hx, lx, hy, ly, hz, lz, hw, lw;
    split1(acc.x, hx, lx); split1(acc.y, hy, ly);
    split1(acc.z, hz, lz); split1(acc.w, hw, lw);
    uint32_t h01 = ((uint32_t)__bfloat16_as_ushort(hy) << 16) | __bfloat16_as_ushort(hx);
    uint32_t h23 = ((uint32_t)__bfloat16_as_ushort(hw) << 16) | __bfloat16_as_ushort(hz);
    uint32_t l01 = ((uint32_t)__bfloat16_as_ushort(ly) << 16) | __bfloat16_as_ushort(lx);
    uint32_t l23 = ((uint32_t)__bfloat16_as_ushort(lw) << 16) | __bfloat16_as_ushort(lz);
    size_t idx = base + (size_t)n * C4 + t;
    ((uint2*)oh)[idx] = make_uint2(h01, h23);
    ((uint2*)ol)[idx] = make_uint2(l01, l23);
}

// ---------------- shared GEMM mainloop (R7, proven) -------------------------
__device__ __forceinline__ void gemm_body(
    uint32_t sb, int tid,
    const __nv_bfloat16* __restrict__ Ah, const __nv_bfloat16* __restrict__ Al,
    const __nv_bfloat16* __restrict__ Bh, const __nv_bfloat16* __restrict__ Bl,
    int bm, int bn, float acc[4][8][4])
{
    int wid = tid >> 5, lane = tid & 31;

    const __nv_bfloat16* psrc[12];
    uint32_t pdst[12];
#pragma unroll
    for (int j = 0; j < 12; j++) {
        int c = tid + j * 256;
        const __nv_bfloat16* base;
        int row, r0;
        uint32_t off;
        if (c < 512)       { base = Ah; row = c >> 2;          r0 = bm; off = OFF_AH; }
        else if (c < 1024) { base = Al; row = (c - 512) >> 2;  r0 = bm; off = OFF_AL; }
        else if (c < 2048) { base = Bh; row = (c - 1024) >> 2; r0 = bn; off = OFF_BH; }
        else               { base = Bl; row = (c - 2048) >> 2; r0 = bn; off = OFF_BL; }
        int sl = c & 3;
        psrc[j] = base + (size_t)(r0 + row) * CIN + sl * 8;
        pdst[j] = off + (uint32_t)(row * ROWPITCH + sl * 16);
    }

#define ISSUE(stg, kt)                                                     \
    {                                                                      \
        uint32_t stb_ = sb + (stg) * STG_BYTES;                            \
        _Pragma("unroll")                                                  \
        for (int j = 0; j < 12; j++)                                       \
            cp16(stb_ + pdst[j], psrc[j] + (kt) * BKt);                    \
        CP_COMMIT();                                                       \
    }

    ISSUE(0, 0);
    ISSUE(1, 1);

    int wm = wid & 1, wn = wid >> 1;
    uint32_t a_base = (uint32_t)((wm * 64 + (lane & 15)) * ROWPITCH + ((lane >> 4) << 4));
    uint32_t b_base = (uint32_t)(OFF_BH +
        (wn * 64 + ((lane & 7) | ((lane >> 4) << 3))) * ROWPITCH + (((lane >> 3) & 1) << 4));

    for (int kt = 0; kt < NKT; kt++) {
        if (kt + 1 < NKT) CP_WAIT1(); else CP_WAIT0();
        __syncthreads();
        if (kt + 2 < NKT) ISSUE((kt + 2) % NSTAGE, kt + 2);

        uint32_t st = sb + (kt % NSTAGE) * STG_BYTES;
#pragma unroll
        for (int ks = 0; ks < 2; ks++) {
            uint32_t ah[4][4], al[4][4], bh[8][2];
            uint32_t ak = st + a_base + ks * 32;
#pragma unroll
            for (int mi = 0; mi < 4; mi++) {
                LDSM4(ah[mi][0], ah[mi][1], ah[mi][2], ah[mi][3], ak + mi * (16 * ROWPITCH));
                LDSM4(al[mi][0], al[mi][1], al[mi][2], al[mi][3],
                      ak + (OFF_AL - OFF_AH) + mi * (16 * ROWPITCH));
            }
            uint32_t bk = st + b_base + ks * 32;
#pragma unroll
            for (int j = 0; j < 4; j++) {
                uint32_t r0, r1, r2, r3;
                LDSM4(r0, r1, r2, r3, bk + j * (16 * ROWPITCH));
                bh[j * 2][0] = r0;     bh[j * 2][1] = r1;
                bh[j * 2 + 1][0] = r2; bh[j * 2 + 1][1] = r3;
            }
#pragma unroll
            for (int mi = 0; mi < 4; mi++)
#pragma unroll
                for (int nt = 0; nt < 8; nt++)
                    MMA(acc[mi][nt], ah[mi], bh[nt][0], bh[nt][1]);
#pragma unroll
            for (int mi = 0; mi < 4; mi++)
#pragma unroll
                for (int nt = 0; nt < 8; nt++)
                    MMA(acc[mi][nt], al[mi], bh[nt][0], bh[nt][1]);
            uint32_t bl[8][2];
#pragma unroll
            for (int j = 0; j < 4; j++) {
                uint32_t r0, r1, r2, r3;
                LDSM4(r0, r1, r2, r3, bk + (OFF_BL - OFF_BH) + j * (16 * ROWPITCH));
                bl[j * 2][0] = r0;     bl[j * 2][1] = r1;
                bl[j * 2 + 1][0] = r2; bl[j * 2 + 1][1] = r3;
            }
#pragma unroll
            for (int mi = 0; mi < 4; mi++)
#pragma unroll
                for (int nt = 0; nt < 8; nt++)
                    MMA(acc[mi][nt], ah[mi], bl[nt][0], bl[nt][1]);
        }
    }
#undef ISSUE
}

// ---------------- merged GEMM1 + GEMM2 kernel -------------------------------
// role 0 (blockIdx.x < NB1): H1[m][HIDF] = relu(S@W1 + b1) + xt   (direct R7 EPI)
// role 1:                    orT[f][MROWS] = (xt@Wl + bl)^T       (staged)
__global__ __launch_bounds__(256, 1) void k_g12(
    const __nv_bfloat16* __restrict__ Sh, const __nv_bfloat16* __restrict__ Sl,
    const __nv_bfloat16* __restrict__ W1h, const __nv_bfloat16* __restrict__ W1l,
    const float* __restrict__ b1, const float* __restrict__ xt,
    float* __restrict__ H1,
    const __nv_bfloat16* __restrict__ xth, const __nv_bfloat16* __restrict__ xtl,
    const __nv_bfloat16* __restrict__ Wlh, const __nv_bfloat16* __restrict__ Wll,
    const float* __restrict__ bl_, float* __restrict__ orT)
{
    extern __shared__ char smem[];
    uint32_t sb = smem_u32(smem);
    int tid = threadIdx.x, wid = tid >> 5, lane = tid & 31;
    int role = (blockIdx.x < NB1) ? 0 : 1;
    int bm = blockIdx.y * BMt;
    int bn = (role == 0) ? blockIdx.x * BNt : (blockIdx.x - NB1) * BNt;

    float acc[4][8][4];
#pragma unroll
    for (int mi = 0; mi < 4; mi++)
#pragma unroll
        for (int nt = 0; nt < 8; nt++)
#pragma unroll
            for (int q = 0; q < 4; q++) acc[mi][nt][q] = 0.f;

    if (role == 0)
        gemm_body(sb, tid, Sh, Sl, W1h, W1l, bm, bn, acc);
    else
        gemm_body(sb, tid, xth, xtl, Wlh, Wll, bm, bn, acc);

    int wm = wid & 1, wn = wid >> 1;

    if (role == 0) {
        // direct R7 EPI0: relu(acc+b1) + xt, row-major
#pragma unroll
        for (int mi = 0; mi < 4; mi++)
#pragma unroll
            for (int nt = 0; nt < 8; nt++) {
                int m0 = bm + wm * 64 + mi * 16 + (lane >> 2);
                int n0 = bn + wn * 64 + nt * 8 + ((lane & 3) << 1);
                const float* a4 = acc[mi][nt];
                float bs0 = __ldg(&b1[n0]), bs1 = __ldg(&b1[n0 + 1]);
                size_t i0 = (size_t)m0 * HIDF + n0;
                size_t i1 = (size_t)(m0 + 8) * HIDF + n0;
                float2 x0 = *(const float2*)(xt + i0);
                float2 x1 = *(const float2*)(xt + i1);
                *(float2*)(H1 + i0) = make_float2(fmaxf(a4[0] + bs0, 0.f) + x0.x,
                                                  fmaxf(a4[1] + bs1, 0.f) + x0.y);
                *(float2*)(H1 + i1) = make_float2(fmaxf(a4[2] + bs0, 0.f) + x1.x,
                                                  fmaxf(a4[3] + bs1, 0.f) + x1.y);
            }
    } else {
        // staged transpose epilogue -> orT f-major
        __syncthreads();
        float* sep = (float*)smem;
        const int EPP = 130;
        float bf[8][2];
#pragma unroll
        for (int nt = 0; nt < 8; nt++)
#pragma unroll
            for (int ql = 0; ql < 2; ql++)
                bf[nt][ql] = __ldg(&bl_[bn + wn * 64 + nt * 8 + ((lane & 3) << 1) + ql]);
#pragma unroll
        for (int mi = 0; mi < 4; mi++)
#pragma unroll
            for (int nt = 0; nt < 8; nt++)
#pragma unroll
                for (int q = 0; q < 4; q++) {
                    int m_l = wm * 64 + mi * 16 + (lane >> 2) + ((q >> 1) << 3);
                    int f_l = wn * 64 + nt * 8 + ((lane & 3) << 1) + (q & 1);
                    sep[f_l * EPP + m_l] = acc[mi][nt][q] + bf[nt][q & 1];
                }
        __syncthreads();
#pragma unroll 1
        for (int rr = 0; rr < 32; rr++) {
            int f = wid * 32 + rr;
            size_t rowb = (size_t)(bn + f) * MROWS + bm;
#pragma unroll
            for (int mo = 0; mo < 128; mo += 32)
                orT[rowb + mo + lane] = sep[f * EPP + mo + lane];
        }
    }
}

// ---------------- GEMM3: out = (T@W2 + b2) * origin, NCHW coalesced ---------
__global__ __launch_bounds__(256, 1) void k_g3(
    const __nv_bfloat16* __restrict__ Th, const __nv_bfloat16* __restrict__ Tl,
    const __nv_bfloat16* __restrict__ W2h, const __nv_bfloat16* __restrict__ W2l,
    const float* __restrict__ b2, const float* __restrict__ orT,
    float* __restrict__ out)
{
    extern __shared__ char smem[];
    uint32_t sb = smem_u32(smem);
    int tid = threadIdx.x, wid = tid >> 5, lane = tid & 31;
    int bm = blockIdx.y * BMt, bn = blockIdx.x * BNt;

    float acc[4][8][4];
#pragma unroll
    for (int mi = 0; mi < 4; mi++)
#pragma unroll
        for (int nt = 0; nt < 8; nt++)
#pragma unroll
            for (int q = 0; q < 4; q++) acc[mi][nt][q] = 0.f;

    gemm_body(sb, tid, Th, Tl, W2h, W2l, bm, bn, acc);

    int wm = wid & 1, wn = wid >> 1;
    __syncthreads();
    float* sep = (float*)smem;
    const int EPP = 130;
    float bf[8][2];
#pragma unroll
    for (int nt = 0; nt < 8; nt++)
#pragma unroll
        for (int ql = 0; ql < 2; ql++)
            bf[nt][ql] = __ldg(&b2[bn + wn * 64 + nt * 8 + ((lane & 3) << 1) + ql]);
#pragma unroll
    for (int mi = 0; mi < 4; mi++)
#pragma unroll
        for (int nt = 0; nt < 8; nt++)
#pragma unroll
            for (int q = 0; q < 4; q++) {
                int m_l = wm * 64 + mi * 16 + (lane >> 2) + ((q >> 1) << 3);
                int f_l = wn * 64 + nt * 8 + ((lane & 3) << 1) + (q & 1);
                sep[f_l * EPP + m_l] = acc[mi][nt][q] + bf[nt][q & 1];
            }
    __syncthreads();

    int b0 = bm >> 12, nn0 = bm & (NN - 1);
#pragma unroll 1
    for (int rr = 0; rr < 32; rr++) {
        int f = wid * 32 + rr;
        int g = bn + f;
        size_t arow = (size_t)g * MROWS + bm;
        size_t orow = ((size_t)(b0 * OUTF + g)) * NN + nn0;
#pragma unroll
        for (int mo = 0; mo < 128; mo += 32) {
            int m = mo + lane;
            out[orow + m] = sep[f * EPP + m] * orT[arow + m];
        }
    }
}

// ---------------- launch -----------------------------------------------------
extern "C" void kernel_launch(void* const* d_in, const int* in_sizes, int n_in,
                              void* d_out, int out_size) {
    const float* x  = (const float*)d_in[0];
    const float* W1 = (const float*)d_in[1];
    const float* b1 = (const float*)d_in[2];
    const float* W2 = (const float*)d_in[3];
    const float* b2 = (const float*)d_in[4];
    const float* Wl = (const float*)d_in[5];
    const float* bl = (const float*)d_in[6];
    float* out = (float*)d_out;

    float *p_xt, *p_H1, *p_orT;
    __nv_bfloat16 *p_xth, *p_xtl, *p_Sh, *p_Sl, *p_Th, *p_Tl;
    __nv_bfloat16 *p_W1h, *p_W1l, *p_W2h, *p_W2l, *p_Wlh, *p_Wll;
    cudaGetSymbolAddress((void**)&p_xt,  g_xt);
    cudaGetSymbolAddress((void**)&p_xth, g_xth);
    cudaGetSymbolAddress((void**)&p_xtl, g_xtl);
    cudaGetSymbolAddress((void**)&p_Sh,  g_Sh);
    cudaGetSymbolAddress((void**)&p_Sl,  g_Sl);
    cudaGetSymbolAddress((void**)&p_H1,  g_H1);
    cudaGetSymbolAddress((void**)&p_Th,  g_Th);
    cudaGetSymbolAddress((void**)&p_Tl,  g_Tl);
    cudaGetSymbolAddress((void**)&p_orT, g_orT);
    cudaGetSymbolAddress((void**)&p_W1h, g_W1h);
    cudaGetSymbolAddress((void**)&p_W1l, g_W1l);
    cudaGetSymbolAddress((void**)&p_W2h, g_W2h);
    cudaGetSymbolAddress((void**)&p_W2l, g_W2l);
    cudaGetSymbolAddress((void**)&p_Wlh, g_Wlh);
    cudaGetSymbolAddress((void**)&p_Wll, g_Wll);

    cudaFuncSetAttribute(k_g12, cudaFuncAttributeMaxDynamicSharedMemorySize, SMEM_GMM);
    cudaFuncSetAttribute(k_g3,  cudaFuncAttributeMaxDynamicSharedMemorySize, SMEM_GMM);

    // input transpose + split (fp32 + hi/lo, as R7)
    k_tin<<<dim3(NN / 32, CIN / 32, B_), dim3(32, 8)>>>(x);
    // weight transposes + splits
    k_wt<<<dim3(HIDF / 32, CIN / 32), dim3(32, 8)>>>(W1, p_W1h, p_W1l, HIDF);
    k_wt<<<dim3(OUTF / 32, CIN / 32), dim3(32, 8)>>>(W2, p_W2h, p_W2l, OUTF);
    k_wt<<<dim3(OUTF / 32, CIN / 32), dim3(32, 8)>>>(Wl, p_Wlh, p_Wll, OUTF);
    // S = stencil(xt)
    k_st<<<dim3(NN, B_), CIN / 4>>>((const float4*)p_xt, p_Sh, p_Sl);
    // merged: H1 = relu(S@W1+b1)+xt  AND  orT = (xt@Wl+bl)^T
    k_g12<<<dim3(NB1 + OUTF / BNt, MROWS / BMt), 256, SMEM_GMM>>>(
        p_Sh, p_Sl, p_W1h, p_W1l, b1, p_xt, p_H1,
        p_xth, p_xtl, p_Wlh, p_Wll, bl, p_orT);
    // T = stencil(H1)
    k_st<<<dim3(NN, B_), HIDF / 4>>>((const float4*)p_H1, p_Th, p_Tl);
    // out = (T@W2+b2) * origin, coalesced NCHW
    k_g3<<<dim3(OUTF / BNt, MROWS / BMt), 256, SMEM_GMM>>>(
        p_Th, p_Tl, p_W2h, p_W2l, b2, p_orT, out);
}

// round 16
// speedup vs baseline: 1.5677x; 1.2948x over previous
#include <cuda_runtime.h>
#include <cuda_fp16.h>
#include <cstdint>

#define B_    4
#define CIN   1536
#define HIDF  1536
#define OUTF  512
#define HH    64
#define NN    4096
#define MROWS (B_ * NN)      // 16384

// ---------------- GEMM tile config: CTA 128x256, BK32, fp16 A + split-B -----
#define BMt 128
#define BNt 256
#define BKt 32
#define NKT (CIN / BKt)          // 48
#define ROWPITCH 80              // 32 fp16 = 64B data + 16B pad
#define OFF_A  0
#define OFF_BH (128 * ROWPITCH)              // 10240
#define OFF_BL (OFF_BH + 256 * ROWPITCH)     // 30720
#define STG_BYTES (OFF_BL + 256 * ROWPITCH)  // 51200
#define NSTAGE 3
#define SMEM_GMM (NSTAGE * STG_BYTES)        // 153600
#define NB1 (HIDF / BNt)         // 6 role-0 column tiles in merged kernel

// ---------------- scratch ----------------------------------------------------
__device__ float  g_xt [(size_t)MROWS * CIN];
__device__ __half g_xt16[(size_t)MROWS * CIN];
__device__ __half g_S16 [(size_t)MROWS * CIN];
__device__ float  g_H1 [(size_t)MROWS * HIDF];
__device__ __half g_T16 [(size_t)MROWS * HIDF];
__device__ float  g_orT[(size_t)OUTF * MROWS];   // origin f-major [f][m]
__device__ __half g_W1h[(size_t)HIDF * CIN];
__device__ __half g_W1l[(size_t)HIDF * CIN];
__device__ __half g_W2h[(size_t)OUTF * CIN];
__device__ __half g_W2l[(size_t)OUTF * CIN];
__device__ __half g_Wlh[(size_t)OUTF * CIN];
__device__ __half g_Wll[(size_t)OUTF * CIN];

// ---------------- helpers ----------------------------------------------------
__device__ __forceinline__ uint32_t smem_u32(const void* p) {
    uint32_t a;
    asm("{ .reg .u64 t; cvta.to.shared.u64 t, %1; cvt.u32.u64 %0, t; }" : "=r"(a) : "l"(p));
    return a;
}
__device__ __forceinline__ void cp16(uint32_t dst, const void* src) {
    asm volatile("cp.async.cg.shared.global [%0], [%1], 16;" :: "r"(dst), "l"(src));
}
#define CP_COMMIT() asm volatile("cp.async.commit_group;" ::: "memory")
#define CP_WAIT1()  asm volatile("cp.async.wait_group 1;" ::: "memory")
#define CP_WAIT0()  asm volatile("cp.async.wait_group 0;" ::: "memory")

#define LDSM4(r0, r1, r2, r3, a)                                           \
    asm volatile("ldmatrix.sync.aligned.m8n8.x4.shared.b16 {%0,%1,%2,%3}, [%4];" \
                 : "=r"(r0), "=r"(r1), "=r"(r2), "=r"(r3) : "r"(a))

#define MMA(d, a, b0, b1)                                                  \
    asm volatile("mma.sync.aligned.m16n8k16.row.col.f32.f16.f16.f32 "      \
                 "{%0,%1,%2,%3},{%4,%5,%6,%7},{%8,%9},{%0,%1,%2,%3};"      \
                 : "+f"((d)[0]), "+f"((d)[1]), "+f"((d)[2]), "+f"((d)[3])  \
                 : "r"((a)[0]), "r"((a)[1]), "r"((a)[2]), "r"((a)[3]),     \
                   "r"(b0), "r"(b1))

__device__ __forceinline__ void splith(float v, __half& h, __half& l) {
    h = __float2half_rn(v);
    l = __float2half_rn(v - __half2float(h));
}

// ---------------- transpose in: x [B,C,N] -> xt fp32 + fp16 -----------------
__global__ void k_tin(const float* __restrict__ x) {
    __shared__ float tile[32][33];
    int b = blockIdx.z, n0 = blockIdx.x << 5, c0 = blockIdx.y << 5;
    int tx = threadIdx.x, ty = threadIdx.y;
    const float* xb = x + (size_t)b * CIN * NN;
#pragma unroll
    for (int i = ty; i < 32; i += 8)
        tile[i][tx] = xb[(size_t)(c0 + i) * NN + (n0 + tx)];
    __syncthreads();
    size_t ob = (size_t)b * NN * CIN;
#pragma unroll
    for (int i = ty; i < 32; i += 8) {
        float v = tile[tx][i];
        size_t idx = ob + (size_t)(n0 + i) * CIN + (c0 + tx);
        g_xt[idx] = v;
        g_xt16[idx] = __float2half_rn(v);
    }
}

// ---------------- weight prep: W [K,Nc] -> Wt fp16 hi/lo [Nc,K] -------------
__global__ void k_wt(const float* __restrict__ W, __half* __restrict__ oh,
                     __half* __restrict__ ol, int Nc) {
    __shared__ float tile[32][33];
    int n0 = blockIdx.x << 5, k0 = blockIdx.y << 5;
    int tx = threadIdx.x, ty = threadIdx.y;
#pragma unroll
    for (int i = ty; i < 32; i += 8)
        tile[i][tx] = W[(size_t)(k0 + i) * Nc + (n0 + tx)];
    __syncthreads();
#pragma unroll
    for (int i = ty; i < 32; i += 8) {
        float v = tile[tx][i];
        size_t idx = (size_t)(n0 + i) * CIN + (k0 + tx);
        __half h, l; splith(v, h, l);
        oh[idx] = h; ol[idx] = l;
    }
}

// ---------------- 5-point GCN stencil (fp32 in) -> fp16 ---------------------
__device__ __forceinline__ int degat(int r, int c) {
    return 1 + (r > 0) + (r < HH - 1) + (c > 0) + (c < HH - 1);
}

__global__ void k_st(const float4* __restrict__ in, __half* __restrict__ o16) {
    const int C4 = CIN / 4;
    int n = blockIdx.x, b = blockIdx.y, t = threadIdx.x;
    int r = n >> 6, c = n & 63;
    int dg = degat(r, c);
    size_t base = (size_t)b * NN * C4;
    const float4* pin = in + base;

    float4 v = pin[(size_t)n * C4 + t];
    float wc = 1.0f / (float)dg;
    float4 acc = make_float4(v.x * wc, v.y * wc, v.z * wc, v.w * wc);
#define NBR(nm, dr, dc)                                      \
    {                                                        \
        int dn = degat(r + (dr), c + (dc));                  \
        float w = rsqrtf((float)(dg * dn));                  \
        float4 u = pin[(size_t)(nm) * C4 + t];               \
        acc.x += u.x * w; acc.y += u.y * w;                  \
        acc.z += u.z * w; acc.w += u.w * w;                  \
    }
    if (r > 0)  NBR(n - 64, -1, 0);
    if (r < 63) NBR(n + 64, +1, 0);
    if (c > 0)  NBR(n - 1, 0, -1);
    if (c < 63) NBR(n + 1, 0, +1);
#undef NBR
    __half2 p01 = __floats2half2_rn(acc.x, acc.y);
    __half2 p23 = __floats2half2_rn(acc.z, acc.w);
    size_t idx = base + (size_t)n * C4 + t;
    ((uint2*)o16)[idx] = make_uint2(*(uint32_t*)&p01, *(uint32_t*)&p23);
}

// ---------------- shared GEMM mainloop: fp16 A x (Bh + Bl) ------------------
__device__ __forceinline__ void gemm_body(
    uint32_t sb, int tid,
    const __half* __restrict__ A16,
    const __half* __restrict__ Bh, const __half* __restrict__ Bl,
    int bm, int bn, float acc[4][8][4])
{
    int wid = tid >> 5, lane = tid & 31;

    // 10 x 16B cp.async per thread per stage (2560 chunks total)
    const __half* psrc[10];
    uint32_t pdst[10];
#pragma unroll
    for (int j = 0; j < 10; j++) {
        int c = tid + j * 256;           // 0..2559
        const __half* base;
        int row, r0;
        uint32_t off;
        if (c < 512)       { base = A16; row = c >> 2;          r0 = bm; off = OFF_A;  }
        else if (c < 1536) { base = Bh;  row = (c - 512) >> 2;  r0 = bn; off = OFF_BH; }
        else               { base = Bl;  row = (c - 1536) >> 2; r0 = bn; off = OFF_BL; }
        int sl = c & 3;
        psrc[j] = base + (size_t)(r0 + row) * CIN + sl * 8;
        pdst[j] = off + (uint32_t)(row * ROWPITCH + sl * 16);
    }

#define ISSUE(stg, kt)                                                     \
    {                                                                      \
        uint32_t stb_ = sb + (stg) * STG_BYTES;                            \
        _Pragma("unroll")                                                  \
        for (int j = 0; j < 10; j++)                                       \
            cp16(stb_ + pdst[j], psrc[j] + (kt) * BKt);                    \
        CP_COMMIT();                                                       \
    }

    ISSUE(0, 0);
    ISSUE(1, 1);

    int wm = wid & 1, wn = wid >> 1;
    uint32_t a_base = (uint32_t)(OFF_A +
        (wm * 64 + (lane & 15)) * ROWPITCH + ((lane >> 4) << 4));
    uint32_t b_base = (uint32_t)(OFF_BH +
        (wn * 64 + ((lane & 7) | ((lane >> 4) << 3))) * ROWPITCH + (((lane >> 3) & 1) << 4));

    for (int kt = 0; kt < NKT; kt++) {
        if (kt + 1 < NKT) CP_WAIT1(); else CP_WAIT0();
        __syncthreads();
        if (kt + 2 < NKT) ISSUE((kt + 2) % NSTAGE, kt + 2);

        uint32_t st = sb + (kt % NSTAGE) * STG_BYTES;
#pragma unroll
        for (int ks = 0; ks < 2; ks++) {
            uint32_t ah[4][4], bh[8][2], bl[8][2];
            uint32_t ak = st + a_base + ks * 32;
#pragma unroll
            for (int mi = 0; mi < 4; mi++)
                LDSM4(ah[mi][0], ah[mi][1], ah[mi][2], ah[mi][3], ak + mi * (16 * ROWPITCH));
            uint32_t bk = st + b_base + ks * 32;
#pragma unroll
            for (int j = 0; j < 4; j++) {
                uint32_t r0, r1, r2, r3;
                LDSM4(r0, r1, r2, r3, bk + j * (16 * ROWPITCH));
                bh[j * 2][0] = r0;     bh[j * 2][1] = r1;
                bh[j * 2 + 1][0] = r2; bh[j * 2 + 1][1] = r3;
                LDSM4(r0, r1, r2, r3, bk + (OFF_BL - OFF_BH) + j * (16 * ROWPITCH));
                bl[j * 2][0] = r0;     bl[j * 2][1] = r1;
                bl[j * 2 + 1][0] = r2; bl[j * 2 + 1][1] = r3;
            }
#pragma unroll
            for (int mi = 0; mi < 4; mi++)
#pragma unroll
                for (int nt = 0; nt < 8; nt++)
                    MMA(acc[mi][nt], ah[mi], bh[nt][0], bh[nt][1]);
#pragma unroll
            for (int mi = 0; mi < 4; mi++)
#pragma unroll
                for (int nt = 0; nt < 8; nt++)
                    MMA(acc[mi][nt], ah[mi], bl[nt][0], bl[nt][1]);
        }
    }
#undef ISSUE
}

// ---------------- merged GEMM1 + GEMM2 kernel -------------------------------
// role 0 (blockIdx.x < NB1): H1[m][HIDF] = relu(S@W1 + b1) + xt   (direct EPI)
// role 1:                    orT[f][MROWS] = (xt@Wl + bl)^T       (staged)
__global__ __launch_bounds__(256, 1) void k_g12(
    const __half* __restrict__ S16,
    const __half* __restrict__ W1h, const __half* __restrict__ W1l,
    const float* __restrict__ b1, const float* __restrict__ xt,
    float* __restrict__ H1,
    const __half* __restrict__ xt16,
    const __half* __restrict__ Wlh, const __half* __restrict__ Wll,
    const float* __restrict__ bl_, float* __restrict__ orT)
{
    extern __shared__ char smem[];
    uint32_t sb = smem_u32(smem);
    int tid = threadIdx.x, wid = tid >> 5, lane = tid & 31;
    int role = (blockIdx.x < NB1) ? 0 : 1;
    int bm = blockIdx.y * BMt;
    int bn = (role == 0) ? blockIdx.x * BNt : (blockIdx.x - NB1) * BNt;

    float acc[4][8][4];
#pragma unroll
    for (int mi = 0; mi < 4; mi++)
#pragma unroll
        for (int nt = 0; nt < 8; nt++)
#pragma unroll
            for (int q = 0; q < 4; q++) acc[mi][nt][q] = 0.f;

    if (role == 0)
        gemm_body(sb, tid, S16, W1h, W1l, bm, bn, acc);
    else
        gemm_body(sb, tid, xt16, Wlh, Wll, bm, bn, acc);

    int wm = wid & 1, wn = wid >> 1;

    if (role == 0) {
        // direct EPI: relu(acc+b1) + xt, row-major fp32
#pragma unroll
        for (int mi = 0; mi < 4; mi++)
#pragma unroll
            for (int nt = 0; nt < 8; nt++) {
                int m0 = bm + wm * 64 + mi * 16 + (lane >> 2);
                int n0 = bn + wn * 64 + nt * 8 + ((lane & 3) << 1);
                const float* a4 = acc[mi][nt];
                float bs0 = __ldg(&b1[n0]), bs1 = __ldg(&b1[n0 + 1]);
                size_t i0 = (size_t)m0 * HIDF + n0;
                size_t i1 = (size_t)(m0 + 8) * HIDF + n0;
                float2 x0 = *(const float2*)(xt + i0);
                float2 x1 = *(const float2*)(xt + i1);
                *(float2*)(H1 + i0) = make_float2(fmaxf(a4[0] + bs0, 0.f) + x0.x,
                                                  fmaxf(a4[1] + bs1, 0.f) + x0.y);
                *(float2*)(H1 + i1) = make_float2(fmaxf(a4[2] + bs0, 0.f) + x1.x,
                                                  fmaxf(a4[3] + bs1, 0.f) + x1.y);
            }
    } else {
        // staged transpose epilogue -> orT f-major
        __syncthreads();
        float* sep = (float*)smem;
        const int EPP = 130;
        float bf[8][2];
#pragma unroll
        for (int nt = 0; nt < 8; nt++)
#pragma unroll
            for (int ql = 0; ql < 2; ql++)
                bf[nt][ql] = __ldg(&bl_[bn + wn * 64 + nt * 8 + ((lane & 3) << 1) + ql]);
#pragma unroll
        for (int mi = 0; mi < 4; mi++)
#pragma unroll
            for (int nt = 0; nt < 8; nt++)
#pragma unroll
                for (int q = 0; q < 4; q++) {
                    int m_l = wm * 64 + mi * 16 + (lane >> 2) + ((q >> 1) << 3);
                    int f_l = wn * 64 + nt * 8 + ((lane & 3) << 1) + (q & 1);
                    sep[f_l * EPP + m_l] = acc[mi][nt][q] + bf[nt][q & 1];
                }
        __syncthreads();
#pragma unroll 1
        for (int rr = 0; rr < 32; rr++) {
            int f = wid * 32 + rr;
            size_t rowb = (size_t)(bn + f) * MROWS + bm;
#pragma unroll
            for (int mo = 0; mo < 128; mo += 32)
                orT[rowb + mo + lane] = sep[f * EPP + mo + lane];
        }
    }
}

// ---------------- GEMM3: out = (T@W2 + b2) * origin, NCHW coalesced ---------
__global__ __launch_bounds__(256, 1) void k_g3(
    const __half* __restrict__ T16,
    const __half* __restrict__ W2h, const __half* __restrict__ W2l,
    const float* __restrict__ b2, const float* __restrict__ orT,
    float* __restrict__ out)
{
    extern __shared__ char smem[];
    uint32_t sb = smem_u32(smem);
    int tid = threadIdx.x, wid = tid >> 5, lane = tid & 31;
    int bm = blockIdx.y * BMt, bn = blockIdx.x * BNt;

    float acc[4][8][4];
#pragma unroll
    for (int mi = 0; mi < 4; mi++)
#pragma unroll
        for (int nt = 0; nt < 8; nt++)
#pragma unroll
            for (int q = 0; q < 4; q++) acc[mi][nt][q] = 0.f;

    gemm_body(sb, tid, T16, W2h, W2l, bm, bn, acc);

    int wm = wid & 1, wn = wid >> 1;
    __syncthreads();
    float* sep = (float*)smem;
    const int EPP = 130;
    float bf[8][2];
#pragma unroll
    for (int nt = 0; nt < 8; nt++)
#pragma unroll
        for (int ql = 0; ql < 2; ql++)
            bf[nt][ql] = __ldg(&b2[bn + wn * 64 + nt * 8 + ((lane & 3) << 1) + ql]);
#pragma unroll
    for (int mi = 0; mi < 4; mi++)
#pragma unroll
        for (int nt = 0; nt < 8; nt++)
#pragma unroll
            for (int q = 0; q < 4; q++) {
                int m_l = wm * 64 + mi * 16 + (lane >> 2) + ((q >> 1) << 3);
                int f_l = wn * 64 + nt * 8 + ((lane & 3) << 1) + (q & 1);
                sep[f_l * EPP + m_l] = acc[mi][nt][q] + bf[nt][q & 1];
            }
    __syncthreads();

    int b0 = bm >> 12, nn0 = bm & (NN - 1);
#pragma unroll 1
    for (int rr = 0; rr < 32; rr++) {
        int f = wid * 32 + rr;
        int g = bn + f;
        size_t arow = (size_t)g * MROWS + bm;
        size_t orow = ((size_t)(b0 * OUTF + g)) * NN + nn0;
#pragma unroll
        for (int mo = 0; mo < 128; mo += 32) {
            int m = mo + lane;
            out[orow + m] = sep[f * EPP + m] * orT[arow + m];
        }
    }
}

// ---------------- launch -----------------------------------------------------
extern "C" void kernel_launch(void* const* d_in, const int* in_sizes, int n_in,
                              void* d_out, int out_size) {
    const float* x  = (const float*)d_in[0];
    const float* W1 = (const float*)d_in[1];
    const float* b1 = (const float*)d_in[2];
    const float* W2 = (const float*)d_in[3];
    const float* b2 = (const float*)d_in[4];
    const float* Wl = (const float*)d_in[5];
    const float* bl = (const float*)d_in[6];
    float* out = (float*)d_out;

    float *p_xt, *p_H1, *p_orT;
    __half *p_xt16, *p_S16, *p_T16;
    __half *p_W1h, *p_W1l, *p_W2h, *p_W2l, *p_Wlh, *p_Wll;
    cudaGetSymbolAddress((void**)&p_xt,   g_xt);
    cudaGetSymbolAddress((void**)&p_xt16, g_xt16);
    cudaGetSymbolAddress((void**)&p_S16,  g_S16);
    cudaGetSymbolAddress((void**)&p_H1,   g_H1);
    cudaGetSymbolAddress((void**)&p_T16,  g_T16);
    cudaGetSymbolAddress((void**)&p_orT,  g_orT);
    cudaGetSymbolAddress((void**)&p_W1h,  g_W1h);
    cudaGetSymbolAddress((void**)&p_W1l,  g_W1l);
    cudaGetSymbolAddress((void**)&p_W2h,  g_W2h);
    cudaGetSymbolAddress((void**)&p_W2l,  g_W2l);
    cudaGetSymbolAddress((void**)&p_Wlh,  g_Wlh);
    cudaGetSymbolAddress((void**)&p_Wll,  g_Wll);

    cudaFuncSetAttribute(k_g12, cudaFuncAttributeMaxDynamicSharedMemorySize, SMEM_GMM);
    cudaFuncSetAttribute(k_g3,  cudaFuncAttributeMaxDynamicSharedMemorySize, SMEM_GMM);

    // input transpose: fp32 + fp16
    k_tin<<<dim3(NN / 32, CIN / 32, B_), dim3(32, 8)>>>(x);
    // weight transposes + fp16 hi/lo splits
    k_wt<<<dim3(HIDF / 32, CIN / 32), dim3(32, 8)>>>(W1, p_W1h, p_W1l, HIDF);
    k_wt<<<dim3(OUTF / 32, CIN / 32), dim3(32, 8)>>>(W2, p_W2h, p_W2l, OUTF);
    k_wt<<<dim3(OUTF / 32, CIN / 32), dim3(32, 8)>>>(Wl, p_Wlh, p_Wll, OUTF);
    // S = stencil(xt) -> fp16
    k_st<<<dim3(NN, B_), CIN / 4>>>((const float4*)p_xt, p_S16);
    // merged: H1 = relu(S@W1+b1)+xt  AND  orT = (xt@Wl+bl)^T
    k_g12<<<dim3(NB1 + OUTF / BNt, MROWS / BMt), 256, SMEM_GMM>>>(
        p_S16, p_W1h, p_W1l, b1, p_xt, p_H1,
        p_xt16, p_Wlh, p_Wll, bl, p_orT);
    // T = stencil(H1) -> fp16
    k_st<<<dim3(NN, B_), HIDF / 4>>>((const float4*)p_H1, p_T16);
    // out = (T@W2+b2) * origin, coalesced NCHW
    k_g3<<<dim3(OUTF / BNt, MROWS / BMt), 256, SMEM_GMM>>>(
        p_T16, p_W2h, p_W2l, b2, p_orT, out);
}

// round 17
// speedup vs baseline: 2.2858x; 1.4581x over previous
#include <cuda_runtime.h>
#include <cuda_fp16.h>
#include <cstdint>

#define B_    4
#define CIN   1536
#define HIDF  1536
#define OUTF  512
#define HH    64
#define NN    4096
#define MROWS (B_ * NN)      // 16384

// ---------------- GEMM tile config: CTA 128x256, BK32, pure fp16 ------------
#define BMt 128
#define BNt 256
#define BKt 32
#define NKT (CIN / BKt)          // 48
#define ROWPITCH 80              // 32 fp16 = 64B data + 16B pad
#define OFF_A  0
#define OFF_B  (128 * ROWPITCH)              // 10240
#define STG_BYTES (OFF_B + 256 * ROWPITCH)   // 30720
#define NSTAGE 3
#define SMEM_STAGES (NSTAGE * STG_BYTES)     // 92160
#define SMEM_EPI (256 * 130 * 4)             // 133120 (f-major staging)
#define SMEM_GMM (SMEM_EPI > SMEM_STAGES ? SMEM_EPI : SMEM_STAGES)
#define NB1 (HIDF / BNt)         // 6 role-0 column tiles in merged kernel

// ---------------- scratch ----------------------------------------------------
__device__ float  g_xt [(size_t)MROWS * CIN];
__device__ __half g_xt16[(size_t)MROWS * CIN];
__device__ __half g_S16 [(size_t)MROWS * CIN];
__device__ float  g_H1 [(size_t)MROWS * HIDF];
__device__ __half g_T16 [(size_t)MROWS * HIDF];
__device__ float  g_orT[(size_t)OUTF * MROWS];   // origin f-major [f][m]
__device__ __half g_W1t[(size_t)HIDF * CIN];
__device__ __half g_W2t[(size_t)OUTF * CIN];
__device__ __half g_Wlt[(size_t)OUTF * CIN];

// ---------------- helpers ----------------------------------------------------
__device__ __forceinline__ uint32_t smem_u32(const void* p) {
    uint32_t a;
    asm("{ .reg .u64 t; cvta.to.shared.u64 t, %1; cvt.u32.u64 %0, t; }" : "=r"(a) : "l"(p));
    return a;
}
__device__ __forceinline__ void cp16(uint32_t dst, const void* src) {
    asm volatile("cp.async.cg.shared.global [%0], [%1], 16;" :: "r"(dst), "l"(src));
}
#define CP_COMMIT() asm volatile("cp.async.commit_group;" ::: "memory")
#define CP_WAIT1()  asm volatile("cp.async.wait_group 1;" ::: "memory")
#define CP_WAIT0()  asm volatile("cp.async.wait_group 0;" ::: "memory")

#define LDSM4(r0, r1, r2, r3, a)                                           \
    asm volatile("ldmatrix.sync.aligned.m8n8.x4.shared.b16 {%0,%1,%2,%3}, [%4];" \
                 : "=r"(r0), "=r"(r1), "=r"(r2), "=r"(r3) : "r"(a))

#define MMA(d, a, b0, b1)                                                  \
    asm volatile("mma.sync.aligned.m16n8k16.row.col.f32.f16.f16.f32 "      \
                 "{%0,%1,%2,%3},{%4,%5,%6,%7},{%8,%9},{%0,%1,%2,%3};"      \
                 : "+f"((d)[0]), "+f"((d)[1]), "+f"((d)[2]), "+f"((d)[3])  \
                 : "r"((a)[0]), "r"((a)[1]), "r"((a)[2]), "r"((a)[3]),     \
                   "r"(b0), "r"(b1))

// ---------------- transpose in: x [B,C,N] -> xt fp32 + fp16 -----------------
__global__ void k_tin(const float* __restrict__ x) {
    __shared__ float tile[32][33];
    int b = blockIdx.z, n0 = blockIdx.x << 5, c0 = blockIdx.y << 5;
    int tx = threadIdx.x, ty = threadIdx.y;
    const float* xb = x + (size_t)b * CIN * NN;
#pragma unroll
    for (int i = ty; i < 32; i += 8)
        tile[i][tx] = xb[(size_t)(c0 + i) * NN + (n0 + tx)];
    __syncthreads();
    size_t ob = (size_t)b * NN * CIN;
#pragma unroll
    for (int i = ty; i < 32; i += 8) {
        float v = tile[tx][i];
        size_t idx = ob + (size_t)(n0 + i) * CIN + (c0 + tx);
        g_xt[idx] = v;
        g_xt16[idx] = __float2half_rn(v);
    }
}

// ---------------- weight prep: W [K,Nc] -> Wt fp16 [Nc,K] -------------------
__global__ void k_wt(const float* __restrict__ W, __half* __restrict__ o, int Nc) {
    __shared__ float tile[32][33];
    int n0 = blockIdx.x << 5, k0 = blockIdx.y << 5;
    int tx = threadIdx.x, ty = threadIdx.y;
#pragma unroll
    for (int i = ty; i < 32; i += 8)
        tile[i][tx] = W[(size_t)(k0 + i) * Nc + (n0 + tx)];
    __syncthreads();
#pragma unroll
    for (int i = ty; i < 32; i += 8)
        o[(size_t)(n0 + i) * CIN + (k0 + tx)] = __float2half_rn(tile[tx][i]);
}

// ---------------- 5-point GCN stencil (fp32 in) -> fp16 ---------------------
__device__ __forceinline__ int degat(int r, int c) {
    return 1 + (r > 0) + (r < HH - 1) + (c > 0) + (c < HH - 1);
}

__global__ void k_st(const float4* __restrict__ in, __half* __restrict__ o16) {
    const int C4 = CIN / 4;
    int n = blockIdx.x, b = blockIdx.y, t = threadIdx.x;
    int r = n >> 6, c = n & 63;
    int dg = degat(r, c);
    size_t base = (size_t)b * NN * C4;
    const float4* pin = in + base;

    float4 v = pin[(size_t)n * C4 + t];
    float wc = 1.0f / (float)dg;
    float4 acc = make_float4(v.x * wc, v.y * wc, v.z * wc, v.w * wc);
#define NBR(nm, dr, dc)                                      \
    {                                                        \
        int dn = degat(r + (dr), c + (dc));                  \
        float w = rsqrtf((float)(dg * dn));                  \
        float4 u = pin[(size_t)(nm) * C4 + t];               \
        acc.x += u.x * w; acc.y += u.y * w;                  \
        acc.z += u.z * w; acc.w += u.w * w;                  \
    }
    if (r > 0)  NBR(n - 64, -1, 0);
    if (r < 63) NBR(n + 64, +1, 0);
    if (c > 0)  NBR(n - 1, 0, -1);
    if (c < 63) NBR(n + 1, 0, +1);
#undef NBR
    __half2 p01 = __floats2half2_rn(acc.x, acc.y);
    __half2 p23 = __floats2half2_rn(acc.z, acc.w);
    size_t idx = base + (size_t)n * C4 + t;
    ((uint2*)o16)[idx] = make_uint2(*(uint32_t*)&p01, *(uint32_t*)&p23);
}

// ---------------- shared GEMM mainloop: pure fp16, single MMA ---------------
__device__ __forceinline__ void gemm_body(
    uint32_t sb, int tid,
    const __half* __restrict__ A16, const __half* __restrict__ B16,
    int bm, int bn, float acc[4][8][4])
{
    int wid = tid >> 5, lane = tid & 31;

    // 6 x 16B cp.async per thread per stage (1536 chunks total)
    const __half* psrc[6];
    uint32_t pdst[6];
#pragma unroll
    for (int j = 0; j < 6; j++) {
        int c = tid + j * 256;           // 0..1535
        const __half* base;
        int row, r0;
        uint32_t off;
        if (c < 512) { base = A16; row = c >> 2;         r0 = bm; off = OFF_A; }
        else         { base = B16; row = (c - 512) >> 2; r0 = bn; off = OFF_B; }
        int sl = c & 3;
        psrc[j] = base + (size_t)(r0 + row) * CIN + sl * 8;
        pdst[j] = off + (uint32_t)(row * ROWPITCH + sl * 16);
    }

#define ISSUE(stg, kt)                                                     \
    {                                                                      \
        uint32_t stb_ = sb + (stg) * STG_BYTES;                            \
        _Pragma("unroll")                                                  \
        for (int j = 0; j < 6; j++)                                        \
            cp16(stb_ + pdst[j], psrc[j] + (kt) * BKt);                    \
        CP_COMMIT();                                                       \
    }

    ISSUE(0, 0);
    ISSUE(1, 1);

    int wm = wid & 1, wn = wid >> 1;
    uint32_t a_base = (uint32_t)(OFF_A +
        (wm * 64 + (lane & 15)) * ROWPITCH + ((lane >> 4) << 4));
    uint32_t b_base = (uint32_t)(OFF_B +
        (wn * 64 + ((lane & 7) | ((lane >> 4) << 3))) * ROWPITCH + (((lane >> 3) & 1) << 4));

    for (int kt = 0; kt < NKT; kt++) {
        if (kt + 1 < NKT) CP_WAIT1(); else CP_WAIT0();
        __syncthreads();
        if (kt + 2 < NKT) ISSUE((kt + 2) % NSTAGE, kt + 2);

        uint32_t st = sb + (kt % NSTAGE) * STG_BYTES;
#pragma unroll
        for (int ks = 0; ks < 2; ks++) {
            uint32_t ah[4][4], bh[8][2];
            uint32_t ak = st + a_base + ks * 32;
#pragma unroll
            for (int mi = 0; mi < 4; mi++)
                LDSM4(ah[mi][0], ah[mi][1], ah[mi][2], ah[mi][3], ak + mi * (16 * ROWPITCH));
            uint32_t bk = st + b_base + ks * 32;
#pragma unroll
            for (int j = 0; j < 4; j++) {
                uint32_t r0, r1, r2, r3;
                LDSM4(r0, r1, r2, r3, bk + j * (16 * ROWPITCH));
                bh[j * 2][0] = r0;     bh[j * 2][1] = r1;
                bh[j * 2 + 1][0] = r2; bh[j * 2 + 1][1] = r3;
            }
#pragma unroll
            for (int mi = 0; mi < 4; mi++)
#pragma unroll
                for (int nt = 0; nt < 8; nt++)
                    MMA(acc[mi][nt], ah[mi], bh[nt][0], bh[nt][1]);
        }
    }
#undef ISSUE
}

// ---------------- merged GEMM1 + GEMM2 kernel -------------------------------
// role 0 (blockIdx.x < NB1): H1[m][HIDF] = relu(S@W1 + b1) + xt   (direct EPI)
// role 1:                    orT[f][MROWS] = (xt@Wl + bl)^T       (staged)
__global__ __launch_bounds__(256, 1) void k_g12(
    const __half* __restrict__ S16, const __half* __restrict__ W1t,
    const float* __restrict__ b1, const float* __restrict__ xt,
    float* __restrict__ H1,
    const __half* __restrict__ xt16, const __half* __restrict__ Wlt,
    const float* __restrict__ bl_, float* __restrict__ orT)
{
    extern __shared__ char smem[];
    uint32_t sb = smem_u32(smem);
    int tid = threadIdx.x, wid = tid >> 5, lane = tid & 31;
    int role = (blockIdx.x < NB1) ? 0 : 1;
    int bm = blockIdx.y * BMt;
    int bn = (role == 0) ? blockIdx.x * BNt : (blockIdx.x - NB1) * BNt;

    float acc[4][8][4];
#pragma unroll
    for (int mi = 0; mi < 4; mi++)
#pragma unroll
        for (int nt = 0; nt < 8; nt++)
#pragma unroll
            for (int q = 0; q < 4; q++) acc[mi][nt][q] = 0.f;

    if (role == 0)
        gemm_body(sb, tid, S16, W1t, bm, bn, acc);
    else
        gemm_body(sb, tid, xt16, Wlt, bm, bn, acc);

    int wm = wid & 1, wn = wid >> 1;

    if (role == 0) {
        // direct EPI: relu(acc+b1) + xt, row-major fp32
#pragma unroll
        for (int mi = 0; mi < 4; mi++)
#pragma unroll
            for (int nt = 0; nt < 8; nt++) {
                int m0 = bm + wm * 64 + mi * 16 + (lane >> 2);
                int n0 = bn + wn * 64 + nt * 8 + ((lane & 3) << 1);
                const float* a4 = acc[mi][nt];
                float bs0 = __ldg(&b1[n0]), bs1 = __ldg(&b1[n0 + 1]);
                size_t i0 = (size_t)m0 * HIDF + n0;
                size_t i1 = (size_t)(m0 + 8) * HIDF + n0;
                float2 x0 = *(const float2*)(xt + i0);
                float2 x1 = *(const float2*)(xt + i1);
                *(float2*)(H1 + i0) = make_float2(fmaxf(a4[0] + bs0, 0.f) + x0.x,
                                                  fmaxf(a4[1] + bs1, 0.f) + x0.y);
                *(float2*)(H1 + i1) = make_float2(fmaxf(a4[2] + bs0, 0.f) + x1.x,
                                                  fmaxf(a4[3] + bs1, 0.f) + x1.y);
            }
    } else {
        // staged transpose epilogue -> orT f-major
        __syncthreads();
        float* sep = (float*)smem;
        const int EPP = 130;
        float bf[8][2];
#pragma unroll
        for (int nt = 0; nt < 8; nt++)
#pragma unroll
            for (int ql = 0; ql < 2; ql++)
                bf[nt][ql] = __ldg(&bl_[bn + wn * 64 + nt * 8 + ((lane & 3) << 1) + ql]);
#pragma unroll
        for (int mi = 0; mi < 4; mi++)
#pragma unroll
            for (int nt = 0; nt < 8; nt++)
#pragma unroll
                for (int q = 0; q < 4; q++) {
                    int m_l = wm * 64 + mi * 16 + (lane >> 2) + ((q >> 1) << 3);
                    int f_l = wn * 64 + nt * 8 + ((lane & 3) << 1) + (q & 1);
                    sep[f_l * EPP + m_l] = acc[mi][nt][q] + bf[nt][q & 1];
                }
        __syncthreads();
#pragma unroll 1
        for (int rr = 0; rr < 32; rr++) {
            int f = wid * 32 + rr;
            size_t rowb = (size_t)(bn + f) * MROWS + bm;
#pragma unroll
            for (int mo = 0; mo < 128; mo += 32)
                orT[rowb + mo + lane] = sep[f * EPP + mo + lane];
        }
    }
}

// ---------------- GEMM3: out = (T@W2 + b2) * origin, NCHW coalesced ---------
__global__ __launch_bounds__(256, 1) void k_g3(
    const __half* __restrict__ T16, const __half* __restrict__ W2t,
    const float* __restrict__ b2, const float* __restrict__ orT,
    float* __restrict__ out)
{
    extern __shared__ char smem[];
    uint32_t sb = smem_u32(smem);
    int tid = threadIdx.x, wid = tid >> 5, lane = tid & 31;
    int bm = blockIdx.y * BMt, bn = blockIdx.x * BNt;

    float acc[4][8][4];
#pragma unroll
    for (int mi = 0; mi < 4; mi++)
#pragma unroll
        for (int nt = 0; nt < 8; nt++)
#pragma unroll
            for (int q = 0; q < 4; q++) acc[mi][nt][q] = 0.f;

    gemm_body(sb, tid, T16, W2t, bm, bn, acc);

    int wm = wid & 1, wn = wid >> 1;
    __syncthreads();
    float* sep = (float*)smem;
    const int EPP = 130;
    float bf[8][2];
#pragma unroll
    for (int nt = 0; nt < 8; nt++)
#pragma unroll
        for (int ql = 0; ql < 2; ql++)
            bf[nt][ql] = __ldg(&b2[bn + wn * 64 + nt * 8 + ((lane & 3) << 1) + ql]);
#pragma unroll
    for (int mi = 0; mi < 4; mi++)
#pragma unroll
        for (int nt = 0; nt < 8; nt++)
#pragma unroll
            for (int q = 0; q < 4; q++) {
                int m_l = wm * 64 + mi * 16 + (lane >> 2) + ((q >> 1) << 3);
                int f_l = wn * 64 + nt * 8 + ((lane & 3) << 1) + (q & 1);
                sep[f_l * EPP + m_l] = acc[mi][nt][q] + bf[nt][q & 1];
            }
    __syncthreads();

    int b0 = bm >> 12, nn0 = bm & (NN - 1);
#pragma unroll 1
    for (int rr = 0; rr < 32; rr++) {
        int f = wid * 32 + rr;
        int g = bn + f;
        size_t arow = (size_t)g * MROWS + bm;
        size_t orow = ((size_t)(b0 * OUTF + g)) * NN + nn0;
#pragma unroll
        for (int mo = 0; mo < 128; mo += 32) {
            int m = mo + lane;
            out[orow + m] = sep[f * EPP + m] * orT[arow + m];
        }
    }
}

// ---------------- launch -----------------------------------------------------
extern "C" void kernel_launch(void* const* d_in, const int* in_sizes, int n_in,
                              void* d_out, int out_size) {
    const float* x  = (const float*)d_in[0];
    const float* W1 = (const float*)d_in[1];
    const float* b1 = (const float*)d_in[2];
    const float* W2 = (const float*)d_in[3];
    const float* b2 = (const float*)d_in[4];
    const float* Wl = (const float*)d_in[5];
    const float* bl = (const float*)d_in[6];
    float* out = (float*)d_out;

    float *p_xt, *p_H1, *p_orT;
    __half *p_xt16, *p_S16, *p_T16, *p_W1t, *p_W2t, *p_Wlt;
    cudaGetSymbolAddress((void**)&p_xt,   g_xt);
    cudaGetSymbolAddress((void**)&p_xt16, g_xt16);
    cudaGetSymbolAddress((void**)&p_S16,  g_S16);
    cudaGetSymbolAddress((void**)&p_H1,   g_H1);
    cudaGetSymbolAddress((void**)&p_T16,  g_T16);
    cudaGetSymbolAddress((void**)&p_orT,  g_orT);
    cudaGetSymbolAddress((void**)&p_W1t,  g_W1t);
    cudaGetSymbolAddress((void**)&p_W2t,  g_W2t);
    cudaGetSymbolAddress((void**)&p_Wlt,  g_Wlt);

    cudaFuncSetAttribute(k_g12, cudaFuncAttributeMaxDynamicSharedMemorySize, SMEM_GMM);
    cudaFuncSetAttribute(k_g3,  cudaFuncAttributeMaxDynamicSharedMemorySize, SMEM_GMM);

    // input transpose: fp32 + fp16
    k_tin<<<dim3(NN / 32, CIN / 32, B_), dim3(32, 8)>>>(x);
    // weight transposes -> fp16
    k_wt<<<dim3(HIDF / 32, CIN / 32), dim3(32, 8)>>>(W1, p_W1t, HIDF);
    k_wt<<<dim3(OUTF / 32, CIN / 32), dim3(32, 8)>>>(W2, p_W2t, OUTF);
    k_wt<<<dim3(OUTF / 32, CIN / 32), dim3(32, 8)>>>(Wl, p_Wlt, OUTF);
    // S = stencil(xt) -> fp16
    k_st<<<dim3(NN, B_), CIN / 4>>>((const float4*)p_xt, p_S16);
    // merged: H1 = relu(S@W1+b1)+xt  AND  orT = (xt@Wl+bl)^T
    k_g12<<<dim3(NB1 + OUTF / BNt, MROWS / BMt), 256, SMEM_GMM>>>(
        p_S16, p_W1t, b1, p_xt, p_H1, p_xt16, p_Wlt, bl, p_orT);
    // T = stencil(H1) -> fp16
    k_st<<<dim3(NN, B_), HIDF / 4>>>((const float4*)p_H1, p_T16);
    // out = (T@W2+b2) * origin, coalesced NCHW
    k_g3<<<dim3(OUTF / BNt, MROWS / BMt), 256, SMEM_GMM>>>(
        p_T16, p_W2t, b2, p_orT, out);
}